// round 2
// baseline (speedup 1.0000x reference)
#include <cuda_runtime.h>
#include <math.h>

#define B_DIM 2048
#define N_IN  512
#define N_OUT 512
#define RSQRT2 0.70710678118654752440f

// Normalized xr scratch: (B, N_IN, 8) fp32 = 33.5 MB. Static device global (no runtime alloc).
__device__ float g_xr[(size_t)B_DIM * N_IN * 8];

// ---- Cl(3,0) geometric-product tables, entry e = bi*8 + bk ----
// Blades: 0:1, 1:e1, 2:e2, 3:e3, 4:e12, 5:e13, 6:e23, 7:e123
// c_BJ: output blade of blade_bi * blade_bk
__device__ constexpr int c_BJ[64] = {
    0,1,2,3,4,5,6,7,
    1,0,4,5,2,3,7,6,
    2,4,0,6,1,7,3,5,
    3,5,6,0,7,1,2,4,
    4,2,1,7,0,6,5,3,
    5,3,7,1,6,0,4,2,
    6,7,3,2,5,4,0,1,
    7,6,5,4,3,2,1,0};
// c_P: path index (argwhere order over (gi,gj,gk) grade triples) -> weight channel
__device__ constexpr int c_P[64] = {
     0, 1, 1, 1, 2, 2, 2, 3,
     5, 4, 7, 7, 6, 6, 9, 8,
     5, 7, 4, 7, 6, 9, 6, 8,
     5, 7, 7, 4, 9, 6, 6, 8,
    13,11,11,15,10,14,14,12,
    13,11,15,11,14,10,14,12,
    13,15,11,11,14,14,10,12,
    19,18,18,18,17,17,17,16};
// c_SG: 1 => +1 Cayley sign, 0 => -1
__device__ constexpr int c_SG[64] = {
    1,1,1,1,1,1,1,1,
    1,1,1,1,1,1,1,1,
    1,0,1,1,0,0,1,0,
    1,0,0,1,1,0,0,1,
    1,0,1,1,0,0,1,0,
    1,0,0,1,1,0,0,1,
    1,1,0,1,0,1,0,0,
    1,1,0,1,0,1,0,0};
__device__ constexpr int c_G[8] = {0,1,1,1,2,2,2,3};

// ============================================================================
// Kernel 1: xr[b,m,i] = sum_n x[b,n,i] * w_right[m,n,G[i]]  then grade-normalize.
// Tile 32 (b) x 32 (m), BK=16, 256 threads, 2x2 register tile, 8 blades/output.
// ============================================================================
__global__ __launch_bounds__(256)
void k_xr(const float* __restrict__ x, const float* __restrict__ w_right,
          const float* __restrict__ norm_a)
{
    constexpr int BK = 16;
    constexpr int XS = BK * 8 + 4;   // padded row stride (floats) to break bank conflicts
    constexpr int WS = BK * 4 + 4;
    __shared__ alignas(16) float xs[32 * XS];
    __shared__ alignas(16) float ws[32 * WS];

    const int tid = threadIdx.x;
    const int tx = tid & 15, ty = tid >> 4;
    const int b0 = blockIdx.y * 32, m0 = blockIdx.x * 32;

    float acc[2][2][8];
#pragma unroll
    for (int a = 0; a < 2; a++)
#pragma unroll
        for (int c = 0; c < 2; c++)
#pragma unroll
            for (int i = 0; i < 8; i++) acc[a][c][i] = 0.f;

    for (int kb = 0; kb < N_IN; kb += BK) {
        __syncthreads();
        // x tile: per b, x[b][kb..kb+15][0..7] = 128 contiguous floats = 32 float4
#pragma unroll
        for (int j = 0; j < 4; ++j) {
            int f = tid + j * 256;
            int bb = f >> 5, r = f & 31;
            *(float4*)(xs + bb * XS + r * 4) =
                *(const float4*)(x + ((size_t)(b0 + bb) * N_IN + kb) * 8 + r * 4);
        }
        // w_right tile: per m, 64 contiguous floats = 16 float4
#pragma unroll
        for (int j = 0; j < 2; ++j) {
            int f = tid + j * 256;
            int mm = f >> 4, r = f & 15;
            *(float4*)(ws + mm * WS + r * 4) =
                *(const float4*)(w_right + ((size_t)(m0 + mm) * N_IN + kb) * 4 + r * 4);
        }
        __syncthreads();
#pragma unroll
        for (int k = 0; k < BK; ++k) {
            float xa[2][8], wr[2][4];
#pragma unroll
            for (int a = 0; a < 2; a++) {
                int bb = ty + a * 16;
                *(float4*)(xa[a])     = *(const float4*)(xs + bb * XS + k * 8);
                *(float4*)(xa[a] + 4) = *(const float4*)(xs + bb * XS + k * 8 + 4);
            }
#pragma unroll
            for (int c = 0; c < 2; c++) {
                int mm = tx + c * 16;
                *(float4*)(wr[c]) = *(const float4*)(ws + mm * WS + k * 4);
            }
#pragma unroll
            for (int a = 0; a < 2; a++)
#pragma unroll
                for (int c = 0; c < 2; c++)
#pragma unroll
                    for (int i = 0; i < 8; i++)
                        acc[a][c][i] += xa[a][i] * wr[c][c_G[i]];
        }
    }

    // Epilogue: grade normalization, write g_xr
#pragma unroll
    for (int a = 0; a < 2; a++) {
        int b = b0 + ty + a * 16;
#pragma unroll
        for (int c = 0; c < 2; c++) {
            int m = m0 + tx + c * 16;
            float* A = acc[a][c];
            float n0 = fabsf(A[0]);
            float n1 = sqrtf(A[1]*A[1] + A[2]*A[2] + A[3]*A[3]);
            float n2 = sqrtf(A[4]*A[4] + A[5]*A[5] + A[6]*A[6]);
            float n3 = fabsf(A[7]);
            float4 na = *(const float4*)(norm_a + m * 4);
            float s0 = 1.f / (1.f + expf(-na.x));
            float s1 = 1.f / (1.f + expf(-na.y));
            float s2 = 1.f / (1.f + expf(-na.z));
            float s3 = 1.f / (1.f + expf(-na.w));
            float d0 = 1.f / (s0 * (n0 - 1.f) + 1.f + 1e-6f);
            float d1 = 1.f / (s1 * (n1 - 1.f) + 1.f + 1e-6f);
            float d2 = 1.f / (s2 * (n2 - 1.f) + 1.f + 1e-6f);
            float d3 = 1.f / (s3 * (n3 - 1.f) + 1.f + 1e-6f);
            float* dst = g_xr + ((size_t)b * N_IN + m) * 8;
            *(float4*)(dst)     = make_float4(A[0]*d0, A[1]*d1, A[2]*d1, A[3]*d1);
            *(float4*)(dst + 4) = make_float4(A[4]*d2, A[5]*d2, A[6]*d2, A[7]*d3);
        }
    }
}

// ============================================================================
// Kernel 2: fused bilinear geometric product + left linear + bias + 1/sqrt(2).
// out[b,m,bj] = ( sum_n [ sum_e ±x[b,n,bi]*xr[b,n,bk]*weight[m,n,p(e)]
//                        + x[b,n,i]*w_left[m,n,G[i]] ] + b_left[m]·[i==0] ) / sqrt(2)
// Tile 32 (b) x 32 (m), BK=8, 256 threads, 2x2 register tile, 8-blade accumulators.
// ============================================================================
__global__ __launch_bounds__(256)
void k_main(const float* __restrict__ x, const float* __restrict__ weight,
            const float* __restrict__ w_left, const float* __restrict__ b_left,
            float* __restrict__ out)
{
    constexpr int BK = 8;
    constexpr int XS = BK * 8  + 4;   // 68
    constexpr int WS = BK * 20 + 4;   // 164
    constexpr int LS = BK * 4  + 4;   // 36
    __shared__ alignas(16) float xs[32 * XS];
    __shared__ alignas(16) float rs[32 * XS];
    __shared__ alignas(16) float ws[32 * WS];
    __shared__ alignas(16) float ls[32 * LS];

    const int tid = threadIdx.x;
    const int tx = tid & 15, ty = tid >> 4;
    const int b0 = blockIdx.y * 32, m0 = blockIdx.x * 32;

    float acc[2][2][8];
#pragma unroll
    for (int a = 0; a < 2; a++)
#pragma unroll
        for (int c = 0; c < 2; c++)
#pragma unroll
            for (int i = 0; i < 8; i++) acc[a][c][i] = 0.f;

    for (int kb = 0; kb < N_IN; kb += BK) {
        __syncthreads();
        // x and xr tiles: per b, 64 contiguous floats = 16 float4
#pragma unroll
        for (int j = 0; j < 2; ++j) {
            int f = tid + j * 256;
            int bb = f >> 4, r = f & 15;
            *(float4*)(xs + bb * XS + r * 4) =
                *(const float4*)(x + ((size_t)(b0 + bb) * N_IN + kb) * 8 + r * 4);
            *(float4*)(rs + bb * XS + r * 4) =
                *(const float4*)(g_xr + ((size_t)(b0 + bb) * N_IN + kb) * 8 + r * 4);
        }
        // weight tile: (m,k) rows of 20 floats = 5 float4; 1280 float4 total
#pragma unroll
        for (int j = 0; j < 5; ++j) {
            int f = tid + j * 256;
            int mk = f / 5, q = f - mk * 5;
            int mm = mk >> 3, k = mk & 7;
            *(float4*)(ws + mm * WS + k * 20 + q * 4) =
                *(const float4*)(weight + ((size_t)(m0 + mm) * N_IN + kb + k) * 20 + q * 4);
        }
        // w_left tile: (m,k) rows of 4 floats
        {
            int mm = tid >> 3, k = tid & 7;
            *(float4*)(ls + mm * LS + k * 4) =
                *(const float4*)(w_left + ((size_t)(m0 + mm) * N_IN + kb + k) * 4);
        }
        __syncthreads();

#pragma unroll
        for (int k = 0; k < BK; ++k) {
            float xA[2][8], xR[2][8], w[2][20], wl[2][4];
#pragma unroll
            for (int a = 0; a < 2; a++) {
                int bb = ty + a * 16;
                *(float4*)(xA[a])     = *(const float4*)(xs + bb * XS + k * 8);
                *(float4*)(xA[a] + 4) = *(const float4*)(xs + bb * XS + k * 8 + 4);
                *(float4*)(xR[a])     = *(const float4*)(rs + bb * XS + k * 8);
                *(float4*)(xR[a] + 4) = *(const float4*)(rs + bb * XS + k * 8 + 4);
            }
#pragma unroll
            for (int c = 0; c < 2; c++) {
                int mm = tx + c * 16;
#pragma unroll
                for (int q = 0; q < 5; q++)
                    *(float4*)(w[c] + q * 4) = *(const float4*)(ws + mm * WS + k * 20 + q * 4);
                *(float4*)(wl[c]) = *(const float4*)(ls + mm * LS + k * 4);
            }
            // 64 Cayley entries: signs fold into FFMA negation (free)
#pragma unroll
            for (int e = 0; e < 64; ++e) {
                const int bi = e >> 3, bk = e & 7;
                const int bj = c_BJ[e], pp = c_P[e];
                float p0 = xA[0][bi] * xR[0][bk];
                float p1 = xA[1][bi] * xR[1][bk];
                if (c_SG[e]) {
                    acc[0][0][bj] += p0 * w[0][pp];
                    acc[0][1][bj] += p0 * w[1][pp];
                    acc[1][0][bj] += p1 * w[0][pp];
                    acc[1][1][bj] += p1 * w[1][pp];
                } else {
                    acc[0][0][bj] -= p0 * w[0][pp];
                    acc[0][1][bj] -= p0 * w[1][pp];
                    acc[1][0][bj] -= p1 * w[0][pp];
                    acc[1][1][bj] -= p1 * w[1][pp];
                }
            }
            // left linear term
#pragma unroll
            for (int i = 0; i < 8; ++i) {
                const int g = c_G[i];
                acc[0][0][i] += xA[0][i] * wl[0][g];
                acc[0][1][i] += xA[0][i] * wl[1][g];
                acc[1][0][i] += xA[1][i] * wl[0][g];
                acc[1][1][i] += xA[1][i] * wl[1][g];
            }
        }
    }

    // Epilogue: + b_left on blade 0, scale by 1/sqrt(2), store
#pragma unroll
    for (int a = 0; a < 2; a++) {
        int b = b0 + ty + a * 16;
#pragma unroll
        for (int c = 0; c < 2; c++) {
            int m = m0 + tx + c * 16;
            float* A = acc[a][c];
            A[0] += b_left[m];
            float* dst = out + ((size_t)b * N_OUT + m) * 8;
            *(float4*)(dst)     = make_float4(A[0]*RSQRT2, A[1]*RSQRT2, A[2]*RSQRT2, A[3]*RSQRT2);
            *(float4*)(dst + 4) = make_float4(A[4]*RSQRT2, A[5]*RSQRT2, A[6]*RSQRT2, A[7]*RSQRT2);
        }
    }
}

extern "C" void kernel_launch(void* const* d_in, const int* in_sizes, int n_in,
                              void* d_out, int out_size) {
    const float* x       = (const float*)d_in[0];
    const float* weight  = (const float*)d_in[1];
    const float* w_right = (const float*)d_in[2];
    const float* w_left  = (const float*)d_in[3];
    const float* b_left  = (const float*)d_in[4];
    const float* norm_a  = (const float*)d_in[5];
    float* out = (float*)d_out;

    dim3 grid(N_OUT / 32, B_DIM / 32);   // (16, 64)
    k_xr<<<grid, 256>>>(x, w_right, norm_a);
    k_main<<<grid, 256>>>(x, weight, w_left, b_left, out);
}

// round 7
// speedup vs baseline: 2.3925x; 2.3925x over previous
#include <cuda_runtime.h>
#include <cuda_bf16.h>
#include <math.h>
#include <stdint.h>

#define B_DIM 2048
#define N_IN  512
#define N_OUT 512
#define RSQRT2 0.70710678118654752440f
#define KSL   4608           // 9 * 512, K per phase
#define NKT   216            // 3 phases * 72 k-tiles of 64

// ---------------- device scratch (static globals; no runtime alloc) --------
__device__ float g_xr[(size_t)B_DIM * N_IN * 8];                  // 33.5 MB
__device__ __nv_bfloat16 g_Ah[(size_t)8 * B_DIM * KSL];           // 151 MB
__device__ __nv_bfloat16 g_Al[(size_t)8 * B_DIM * KSL];           // 151 MB
__device__ __nv_bfloat16 g_Bh[(size_t)8 * N_OUT * KSL];           // 37.7 MB
__device__ __nv_bfloat16 g_Bl[(size_t)8 * N_OUT * KSL];           // 37.7 MB
__device__ float g_outT[(size_t)8 * B_DIM * N_OUT];               // 33.5 MB

// ---- Cl(3,0) tables: blades 0:1 1:e1 2:e2 3:e3 4:e12 5:e13 6:e23 7:e123 --
__device__ constexpr int c_P[64] = {
     0, 1, 1, 1, 2, 2, 2, 3,
     5, 4, 7, 7, 6, 6, 9, 8,
     5, 7, 4, 7, 6, 9, 6, 8,
     5, 7, 7, 4, 9, 6, 6, 8,
    13,11,11,15,10,14,14,12,
    13,11,15,11,14,10,14,12,
    13,15,11,11,14,14,10,12,
    19,18,18,18,17,17,17,16};
__device__ constexpr int c_SG[64] = {
    1,1,1,1,1,1,1,1,
    1,1,1,1,1,1,1,1,
    1,0,1,1,0,0,1,0,
    1,0,0,1,1,0,0,1,
    1,0,1,1,0,0,1,0,
    1,0,0,1,1,0,0,1,
    1,1,0,1,0,1,0,0,
    1,1,0,1,0,1,0,0};
__device__ constexpr int c_G[8]  = {0,1,1,1,2,2,2,3};
__device__ constexpr int c_MS[8] = {0,1,2,4,3,5,6,7};

// ---------------- helpers ---------------------------------------------------
__device__ __forceinline__ uint32_t smem_u32(const void* p) {
    uint32_t a;
    asm("{ .reg .u64 t; cvta.to.shared.u64 t, %1; cvt.u32.u64 %0, t; }" : "=r"(a) : "l"(p));
    return a;
}
#define SWZ(o) ((o) ^ (((o) >> 3) & 0x70))

__device__ __forceinline__ void ldm4(uint32_t* r, uint32_t addr) {
    asm volatile("ldmatrix.sync.aligned.m8n8.x4.shared.b16 {%0,%1,%2,%3}, [%4];"
        : "=r"(r[0]), "=r"(r[1]), "=r"(r[2]), "=r"(r[3]) : "r"(addr));
}
__device__ __forceinline__ void mma16816(float* c, const uint32_t* a, uint32_t b0, uint32_t b1) {
    asm volatile(
        "mma.sync.aligned.m16n8k16.row.col.f32.bf16.bf16.f32 "
        "{%0,%1,%2,%3}, {%4,%5,%6,%7}, {%8,%9}, {%0,%1,%2,%3};"
        : "+f"(c[0]), "+f"(c[1]), "+f"(c[2]), "+f"(c[3])
        : "r"(a[0]), "r"(a[1]), "r"(a[2]), "r"(a[3]), "r"(b0), "r"(b1));
}
__device__ __forceinline__ void cp16(uint32_t d, const void* g) {
    asm volatile("cp.async.cg.shared.global [%0], [%1], 16;" :: "r"(d), "l"(g));
}

// ============================================================================
// Kernel 1: xr GEMM (FFMA) + grade normalization epilogue
// ============================================================================
__global__ __launch_bounds__(256)
void k_xr(const float* __restrict__ x, const float* __restrict__ w_right,
          const float* __restrict__ norm_a)
{
    constexpr int BK = 16;
    constexpr int XS = BK * 8 + 4;
    constexpr int WS = BK * 4 + 4;
    __shared__ alignas(16) float xs[32 * XS];
    __shared__ alignas(16) float ws[32 * WS];

    const int tid = threadIdx.x;
    const int tx = tid & 15, ty = tid >> 4;
    const int b0 = blockIdx.y * 32, m0 = blockIdx.x * 32;

    float acc[2][2][8];
#pragma unroll
    for (int a = 0; a < 2; a++)
#pragma unroll
        for (int c = 0; c < 2; c++)
#pragma unroll
            for (int i = 0; i < 8; i++) acc[a][c][i] = 0.f;

    for (int kb = 0; kb < N_IN; kb += BK) {
        __syncthreads();
#pragma unroll
        for (int j = 0; j < 4; ++j) {
            int f = tid + j * 256;
            int bb = f >> 5, r = f & 31;
            *(float4*)(xs + bb * XS + r * 4) =
                *(const float4*)(x + ((size_t)(b0 + bb) * N_IN + kb) * 8 + r * 4);
        }
#pragma unroll
        for (int j = 0; j < 2; ++j) {
            int f = tid + j * 256;
            int mm = f >> 4, r = f & 15;
            *(float4*)(ws + mm * WS + r * 4) =
                *(const float4*)(w_right + ((size_t)(m0 + mm) * N_IN + kb) * 4 + r * 4);
        }
        __syncthreads();
#pragma unroll
        for (int k = 0; k < BK; ++k) {
            float xa[2][8], wr[2][4];
#pragma unroll
            for (int a = 0; a < 2; a++) {
                int bb = ty + a * 16;
                *(float4*)(xa[a])     = *(const float4*)(xs + bb * XS + k * 8);
                *(float4*)(xa[a] + 4) = *(const float4*)(xs + bb * XS + k * 8 + 4);
            }
#pragma unroll
            for (int c = 0; c < 2; c++) {
                int mm = tx + c * 16;
                *(float4*)(wr[c]) = *(const float4*)(ws + mm * WS + k * 4);
            }
#pragma unroll
            for (int a = 0; a < 2; a++)
#pragma unroll
                for (int c = 0; c < 2; c++)
#pragma unroll
                    for (int i = 0; i < 8; i++)
                        acc[a][c][i] += xa[a][i] * wr[c][c_G[i]];
        }
    }

#pragma unroll
    for (int a = 0; a < 2; a++) {
        int b = b0 + ty + a * 16;
#pragma unroll
        for (int c = 0; c < 2; c++) {
            int m = m0 + tx + c * 16;
            float* A = acc[a][c];
            float n0 = fabsf(A[0]);
            float n1 = sqrtf(A[1]*A[1] + A[2]*A[2] + A[3]*A[3]);
            float n2 = sqrtf(A[4]*A[4] + A[5]*A[5] + A[6]*A[6]);
            float n3 = fabsf(A[7]);
            float4 na = *(const float4*)(norm_a + m * 4);
            float s0 = 1.f / (1.f + expf(-na.x));
            float s1 = 1.f / (1.f + expf(-na.y));
            float s2 = 1.f / (1.f + expf(-na.z));
            float s3 = 1.f / (1.f + expf(-na.w));
            float d0 = 1.f / (s0 * (n0 - 1.f) + 1.f + 1e-6f);
            float d1 = 1.f / (s1 * (n1 - 1.f) + 1.f + 1e-6f);
            float d2 = 1.f / (s2 * (n2 - 1.f) + 1.f + 1e-6f);
            float d3 = 1.f / (s3 * (n3 - 1.f) + 1.f + 1e-6f);
            float* dst = g_xr + ((size_t)b * N_IN + m) * 8;
            *(float4*)(dst)     = make_float4(A[0]*d0, A[1]*d1, A[2]*d1, A[3]*d1);
            *(float4*)(dst + 4) = make_float4(A[4]*d2, A[5]*d2, A[6]*d2, A[7]*d3);
        }
    }
}

// ============================================================================
// build A (hi/lo bf16): A[bj][b][t*512+n]: t<8 -> x[b,n,t]*xr[b,n,bk(t,bj)]
//                                           t=8 -> x[b,n,bj]
// ============================================================================
__global__ __launch_bounds__(256)
void k_buildA(const float* __restrict__ x)
{
    int idx = blockIdx.x * 256 + threadIdx.x;
    int b = idx >> 9, n = idx & 511;
    float x8[8], r8[8];
    *(float4*)(x8)     = *(const float4*)(x + (size_t)idx * 8);
    *(float4*)(x8 + 4) = *(const float4*)(x + (size_t)idx * 8 + 4);
    *(float4*)(r8)     = *(const float4*)(g_xr + (size_t)idx * 8);
    *(float4*)(r8 + 4) = *(const float4*)(g_xr + (size_t)idx * 8 + 4);

#pragma unroll
    for (int bj = 0; bj < 8; ++bj) {
        size_t base = ((size_t)bj * B_DIM + b) * KSL + n;
#pragma unroll
        for (int t = 0; t < 9; ++t) {
            float v;
            if (t < 8) {
                int bk = c_MS[c_MS[t] ^ c_MS[bj]];
                v = x8[t] * r8[bk];
            } else {
                v = x8[bj];
            }
            __nv_bfloat16 hi = __float2bfloat16(v);
            __nv_bfloat16 lo = __float2bfloat16(v - __bfloat162float(hi));
            g_Ah[base + (size_t)t * 512] = hi;
            g_Al[base + (size_t)t * 512] = lo;
        }
    }
}

// ============================================================================
// build B (hi/lo bf16): B[bj][m][t*512+n]: t<8 -> sign*weight[m,n,pp(t,bj)]
//                                           t=8 -> w_left[m,n,G[bj]]
// ============================================================================
__global__ __launch_bounds__(256)
void k_buildB(const float* __restrict__ weight, const float* __restrict__ w_left)
{
    int idx = blockIdx.x * 256 + threadIdx.x;
    int m = idx >> 9, n = idx & 511;
    float w[20], wl[4];
#pragma unroll
    for (int q = 0; q < 5; ++q)
        *(float4*)(w + q * 4) = *(const float4*)(weight + (size_t)idx * 20 + q * 4);
    *(float4*)(wl) = *(const float4*)(w_left + (size_t)idx * 4);

#pragma unroll
    for (int bj = 0; bj < 8; ++bj) {
        size_t base = ((size_t)bj * N_OUT + m) * KSL + n;
#pragma unroll
        for (int t = 0; t < 9; ++t) {
            float v;
            if (t < 8) {
                int bk = c_MS[c_MS[t] ^ c_MS[bj]];
                int e = t * 8 + bk;
                v = c_SG[e] ? w[c_P[e]] : -w[c_P[e]];
            } else {
                v = wl[c_G[bj]];
            }
            __nv_bfloat16 hi = __float2bfloat16(v);
            __nv_bfloat16 lo = __float2bfloat16(v - __bfloat162float(hi));
            g_Bh[base + (size_t)t * 512] = hi;
            g_Bl[base + (size_t)t * 512] = lo;
        }
    }
}

// ============================================================================
// mma.sync batched GEMM: g_outT[bj][b][m] = sum_k A[b,k]*B[m,k]  (bf16x3)
// CTA tile 128(b) x 128(m), BK=64, 8 warps of 64x32, 2-stage cp.async pipe.
// grid = (N_OUT/128, B_DIM/128, 8), 256 threads, 64 KB dynamic smem.
// smem: A0@0, A1@16384, B0@32768, B1@49152  (each 128 rows x 128 B, swizzled)
// ============================================================================
__global__ __launch_bounds__(256)
void k_gemm()
{
    extern __shared__ char sm[];
    const uint32_t smb = smem_u32(sm);
    const int tid = threadIdx.x, lane = tid & 31, wid = tid >> 5;
    const int warp_m = wid >> 2, warp_n = wid & 3;
    const int n0 = blockIdx.x * 128, b0 = blockIdx.y * 128;
    const int bj = blockIdx.z;

    const size_t a_row0 = ((size_t)bj * B_DIM + b0) * KSL;
    const size_t b_row0 = ((size_t)bj * N_OUT + n0) * KSL;

    float c[4][4][4];
#pragma unroll
    for (int mi = 0; mi < 4; ++mi)
#pragma unroll
        for (int nn = 0; nn < 4; ++nn)
#pragma unroll
            for (int q = 0; q < 4; ++q) c[mi][nn][q] = 0.f;

    // cp.async per-thread indices: chunk = row(128) x c16(8)
    const int ldrow = tid >> 3, ldc16 = tid & 7;
    const uint32_t ld_sw = SWZ(ldrow * 128 + ldc16 * 16);   // within-tile swizzled offset (rows +32 preserve pattern: +4096)

    // ldmatrix per-thread addressing
    const int a_r = warp_m * 64 + (lane & 7) + ((lane >> 3) & 1) * 8;
    const uint32_t a_lin = a_r * 128, a_sw = (a_r & 7) << 4, a_kl = (lane >> 4) * 16;
    const int b_r = warp_n * 32 + (lane & 7) + (lane >> 4) * 8;
    const uint32_t b_lin = b_r * 128, b_sw = (b_r & 7) << 4, b_kl = ((lane >> 3) & 1) * 16;

    auto load_tiles = [&](int kt, int s) {
        const int phase = kt / 72;
        const int kk = kt - phase * 72;
        const __nv_bfloat16* Ap = (phase == 2) ? g_Al : g_Ah;
        const __nv_bfloat16* Bp = (phase == 1) ? g_Bl : g_Bh;
        const uint32_t sA = smb + s * 16384u;
        const uint32_t sB = smb + 32768u + s * 16384u;
#pragma unroll
        for (int j = 0; j < 4; ++j) {
            int row = ldrow + j * 32;
            cp16(sA + ld_sw + j * 4096u,
                 Ap + a_row0 + (size_t)row * KSL + kk * 64 + ldc16 * 8);
        }
#pragma unroll
        for (int j = 0; j < 4; ++j) {
            int row = ldrow + j * 32;
            cp16(sB + ld_sw + j * 4096u,
                 Bp + b_row0 + (size_t)row * KSL + kk * 64 + ldc16 * 8);
        }
        asm volatile("cp.async.commit_group;");
    };

    auto compute = [&](int s) {
        const uint32_t sA = smb + s * 16384u;
        const uint32_t sB = smb + 32768u + s * 16384u;
#pragma unroll
        for (int k16 = 0; k16 < 4; ++k16) {
            uint32_t af[4][4], bf[2][4];
#pragma unroll
            for (int mi = 0; mi < 4; ++mi)
                ldm4(af[mi], sA + a_lin + mi * 2048u + ((k16 * 32u + a_kl) ^ a_sw));
#pragma unroll
            for (int nj = 0; nj < 2; ++nj)
                ldm4(bf[nj], sB + b_lin + nj * 2048u + ((k16 * 32u + b_kl) ^ b_sw));
#pragma unroll
            for (int mi = 0; mi < 4; ++mi)
#pragma unroll
                for (int nj = 0; nj < 2; ++nj) {
                    mma16816(c[mi][nj * 2 + 0], af[mi], bf[nj][0], bf[nj][1]);
                    mma16816(c[mi][nj * 2 + 1], af[mi], bf[nj][2], bf[nj][3]);
                }
        }
    };

    load_tiles(0, 0);
#pragma unroll 1
    for (int kt = 0; kt < NKT; ++kt) {
        const int s = kt & 1;
        if (kt + 1 < NKT) {
            load_tiles(kt + 1, s ^ 1);
            asm volatile("cp.async.wait_group 1;");
        } else {
            asm volatile("cp.async.wait_group 0;");
        }
        __syncthreads();
        compute(s);
        __syncthreads();
    }

    // epilogue: fragment -> g_outT[bj][b][m]
    float* base = g_outT + (size_t)bj * B_DIM * N_OUT;
    const int mrow = b0 + warp_m * 64 + (lane >> 2);
    const int ncol = n0 + warp_n * 32 + (lane & 3) * 2;
#pragma unroll
    for (int mi = 0; mi < 4; ++mi)
#pragma unroll
        for (int n8 = 0; n8 < 4; ++n8) {
            float* p0 = base + (size_t)(mrow + mi * 16) * N_OUT + ncol + n8 * 8;
            float* p1 = base + (size_t)(mrow + mi * 16 + 8) * N_OUT + ncol + n8 * 8;
            *(float2*)p0 = make_float2(c[mi][n8][0], c[mi][n8][1]);
            *(float2*)p1 = make_float2(c[mi][n8][2], c[mi][n8][3]);
        }
}

// ============================================================================
// merge: out[b][m][bj] = (g_outT[bj][b][m] + (bj==0)*b_left[m]) * RSQRT2
// ============================================================================
__global__ __launch_bounds__(256)
void k_merge(const float* __restrict__ b_left, float* __restrict__ out)
{
    int idx = blockIdx.x * 256 + threadIdx.x;
    int m = idx & 511;
    float v[8];
#pragma unroll
    for (int bj = 0; bj < 8; ++bj)
        v[bj] = g_outT[(size_t)bj * B_DIM * N_OUT + idx];
    v[0] += b_left[m];
    float* dst = out + (size_t)idx * 8;
    *(float4*)(dst)     = make_float4(v[0]*RSQRT2, v[1]*RSQRT2, v[2]*RSQRT2, v[3]*RSQRT2);
    *(float4*)(dst + 4) = make_float4(v[4]*RSQRT2, v[5]*RSQRT2, v[6]*RSQRT2, v[7]*RSQRT2);
}

// ============================================================================
extern "C" void kernel_launch(void* const* d_in, const int* in_sizes, int n_in,
                              void* d_out, int out_size) {
    const float* x       = (const float*)d_in[0];
    const float* weight  = (const float*)d_in[1];
    const float* w_right = (const float*)d_in[2];
    const float* w_left  = (const float*)d_in[3];
    const float* b_left  = (const float*)d_in[4];
    const float* norm_a  = (const float*)d_in[5];
    float* out = (float*)d_out;

    cudaFuncSetAttribute(k_gemm, cudaFuncAttributeMaxDynamicSharedMemorySize, 65536);

    dim3 gxr(N_OUT / 32, B_DIM / 32);
    k_xr<<<gxr, 256>>>(x, w_right, norm_a);
    k_buildB<<<(N_OUT * N_IN) / 256, 256>>>(weight, w_left);
    k_buildA<<<(B_DIM * N_IN) / 256, 256>>>(x);
    dim3 gg(N_OUT / 128, B_DIM / 128, 8);
    k_gemm<<<gg, 256, 65536>>>();
    k_merge<<<(B_DIM * N_OUT) / 256, 256>>>(b_left, out);
}

// round 8
// speedup vs baseline: 3.1732x; 1.3263x over previous
#include <cuda_runtime.h>
#include <cuda_bf16.h>
#include <math.h>
#include <stdint.h>

#define B_DIM 2048
#define N_IN  512
#define N_OUT 512
#define RSQRT2 0.70710678118654752440f
#define KSL   4608           // 9 * 512, K per phase (main GEMM)
#define NKT   216            // 3 phases * 72 k-tiles of 64
#define NKT_XR 24            // 3 phases * 8 k-tiles of 64
#define BN    ((size_t)B_DIM * N_IN)

// ---------------- device scratch (static globals; no runtime alloc) --------
__device__ __nv_bfloat16 g_Ah[(size_t)8 * B_DIM * KSL];           // 151 MB
__device__ __nv_bfloat16 g_Al[(size_t)8 * B_DIM * KSL];           // 151 MB
__device__ __nv_bfloat16 g_Bh[(size_t)8 * N_OUT * KSL];           // 37.7 MB
__device__ __nv_bfloat16 g_Bl[(size_t)8 * N_OUT * KSL];           // 37.7 MB
__device__ float g_outT[(size_t)8 * B_DIM * N_OUT];               // 33.5 MB (xr planes, then out planes)
__device__ __nv_bfloat16 g_xh[(size_t)8 * BN];                    // 16.8 MB
__device__ __nv_bfloat16 g_xl[(size_t)8 * BN];                    // 16.8 MB
__device__ __nv_bfloat16 g_wrh[(size_t)4 * N_IN * N_IN];          // 2.1 MB
__device__ __nv_bfloat16 g_wrl[(size_t)4 * N_IN * N_IN];          // 2.1 MB

// ---- Cl(3,0) tables: blades 0:1 1:e1 2:e2 3:e3 4:e12 5:e13 6:e23 7:e123 --
__device__ constexpr int c_P[64] = {
     0, 1, 1, 1, 2, 2, 2, 3,
     5, 4, 7, 7, 6, 6, 9, 8,
     5, 7, 4, 7, 6, 9, 6, 8,
     5, 7, 7, 4, 9, 6, 6, 8,
    13,11,11,15,10,14,14,12,
    13,11,15,11,14,10,14,12,
    13,15,11,11,14,14,10,12,
    19,18,18,18,17,17,17,16};
__device__ constexpr int c_SG[64] = {
    1,1,1,1,1,1,1,1,
    1,1,1,1,1,1,1,1,
    1,0,1,1,0,0,1,0,
    1,0,0,1,1,0,0,1,
    1,0,1,1,0,0,1,0,
    1,0,0,1,1,0,0,1,
    1,1,0,1,0,1,0,0,
    1,1,0,1,0,1,0,0};
__device__ constexpr int c_G[8]  = {0,1,1,1,2,2,2,3};
__device__ constexpr int c_MS[8] = {0,1,2,4,3,5,6,7};

// ---------------- helpers ---------------------------------------------------
__device__ __forceinline__ uint32_t smem_u32(const void* p) {
    uint32_t a;
    asm("{ .reg .u64 t; cvta.to.shared.u64 t, %1; cvt.u32.u64 %0, t; }" : "=r"(a) : "l"(p));
    return a;
}
#define SWZ(o) ((o) ^ (((o) >> 3) & 0x70))

__device__ __forceinline__ void ldm4(uint32_t* r, uint32_t addr) {
    asm volatile("ldmatrix.sync.aligned.m8n8.x4.shared.b16 {%0,%1,%2,%3}, [%4];"
        : "=r"(r[0]), "=r"(r[1]), "=r"(r[2]), "=r"(r[3]) : "r"(addr));
}
__device__ __forceinline__ void mma16816(float* c, const uint32_t* a, uint32_t b0, uint32_t b1) {
    asm volatile(
        "mma.sync.aligned.m16n8k16.row.col.f32.bf16.bf16.f32 "
        "{%0,%1,%2,%3}, {%4,%5,%6,%7}, {%8,%9}, {%0,%1,%2,%3};"
        : "+f"(c[0]), "+f"(c[1]), "+f"(c[2]), "+f"(c[3])
        : "r"(a[0]), "r"(a[1]), "r"(a[2]), "r"(a[3]), "r"(b0), "r"(b1));
}
__device__ __forceinline__ void cp16(uint32_t d, const void* g) {
    asm volatile("cp.async.cg.shared.global [%0], [%1], 16;" :: "r"(d), "l"(g));
}
#define CP_COMMIT() asm volatile("cp.async.commit_group;")
#define CP_WAIT1()  asm volatile("cp.async.wait_group 1;")
#define CP_WAIT0()  asm volatile("cp.async.wait_group 0;")

__device__ __forceinline__ void bf16_split(float v, __nv_bfloat16& hi, __nv_bfloat16& lo) {
    hi = __float2bfloat16(v);
    lo = __float2bfloat16(v - __bfloat162float(hi));
}

// ============================================================================
// splitX: x[b,n,8] -> g_xh/g_xl planes [i][b][n] (bf16 hi/lo)
// ============================================================================
__global__ __launch_bounds__(256)
void k_splitX(const float* __restrict__ x)
{
    size_t idx = blockIdx.x * 256 + threadIdx.x;    // (b,n)
    float x8[8];
    *(float4*)(x8)     = *(const float4*)(x + idx * 8);
    *(float4*)(x8 + 4) = *(const float4*)(x + idx * 8 + 4);
#pragma unroll
    for (int i = 0; i < 8; ++i) {
        __nv_bfloat16 hi, lo; bf16_split(x8[i], hi, lo);
        g_xh[(size_t)i * BN + idx] = hi;
        g_xl[(size_t)i * BN + idx] = lo;
    }
}

// ============================================================================
// splitW: w_right[m,n,4] -> g_wrh/g_wrl planes [g][m][n]
// ============================================================================
__global__ __launch_bounds__(256)
void k_splitW(const float* __restrict__ w_right)
{
    size_t idx = blockIdx.x * 256 + threadIdx.x;    // (m,n)
    float4 w = *(const float4*)(w_right + idx * 4);
    float w4[4] = {w.x, w.y, w.z, w.w};
#pragma unroll
    for (int g = 0; g < 4; ++g) {
        __nv_bfloat16 hi, lo; bf16_split(w4[g], hi, lo);
        g_wrh[(size_t)g * N_IN * N_IN + idx] = hi;
        g_wrl[(size_t)g * N_IN * N_IN + idx] = lo;
    }
}

// ============================================================================
// xr GEMM (tensor, bf16x3): g_outT[i][b][m] = sum_n x[b,n,i]*w_right[m,n,G[i]]
// CTA 128(b) x 128(m), BK=64, 3-stage cp.async, grid (4, 16, 8).
// ============================================================================
__global__ __launch_bounds__(256)
void k_gemm_xr()
{
    extern __shared__ char sm[];
    const uint32_t smb = smem_u32(sm);
    const int tid = threadIdx.x, lane = tid & 31, wid = tid >> 5;
    const int warp_m = wid >> 2, warp_n = wid & 3;
    const int n0 = blockIdx.x * 128, b0 = blockIdx.y * 128;
    const int ib = blockIdx.z, gg = c_G[ib];

    const size_t a_row0 = ((size_t)ib * B_DIM + b0) * N_IN;
    const size_t b_row0 = ((size_t)gg * N_IN + n0) * N_IN;

    float c[4][4][4];
#pragma unroll
    for (int mi = 0; mi < 4; ++mi)
#pragma unroll
        for (int nn = 0; nn < 4; ++nn)
#pragma unroll
            for (int q = 0; q < 4; ++q) c[mi][nn][q] = 0.f;

    const int ldrow = tid >> 3, ldc16 = tid & 7;
    const uint32_t ld_sw = SWZ(ldrow * 128 + ldc16 * 16);

    const int a_r = warp_m * 64 + (lane & 7) + ((lane >> 3) & 1) * 8;
    const uint32_t a_lin = a_r * 128, a_sw = (a_r & 7) << 4, a_kl = (lane >> 4) * 16;
    const int b_r = warp_n * 32 + (lane & 7) + (lane >> 4) * 8;
    const uint32_t b_lin = b_r * 128, b_sw = (b_r & 7) << 4, b_kl = ((lane >> 3) & 1) * 16;

    auto load_tiles = [&](int kt, int s) {
        const int phase = kt >> 3, kk = kt & 7;
        const __nv_bfloat16* Ap = (phase == 2) ? g_xl : g_xh;
        const __nv_bfloat16* Bp = (phase == 1) ? g_wrl : g_wrh;
        const uint32_t sA = smb + (uint32_t)s * 32768u;
        const uint32_t sB = sA + 16384u;
#pragma unroll
        for (int j = 0; j < 4; ++j) {
            int row = ldrow + j * 32;
            cp16(sA + ld_sw + j * 4096u, Ap + a_row0 + (size_t)row * N_IN + kk * 64 + ldc16 * 8);
            cp16(sB + ld_sw + j * 4096u, Bp + b_row0 + (size_t)row * N_IN + kk * 64 + ldc16 * 8);
        }
        CP_COMMIT();
    };

    auto compute = [&](int s) {
        const uint32_t sA = smb + (uint32_t)s * 32768u;
        const uint32_t sB = sA + 16384u;
#pragma unroll
        for (int k16 = 0; k16 < 4; ++k16) {
            uint32_t af[4][4], bf[2][4];
#pragma unroll
            for (int mi = 0; mi < 4; ++mi)
                ldm4(af[mi], sA + a_lin + mi * 2048u + ((k16 * 32u + a_kl) ^ a_sw));
#pragma unroll
            for (int nj = 0; nj < 2; ++nj)
                ldm4(bf[nj], sB + b_lin + nj * 2048u + ((k16 * 32u + b_kl) ^ b_sw));
#pragma unroll
            for (int mi = 0; mi < 4; ++mi)
#pragma unroll
                for (int nj = 0; nj < 2; ++nj) {
                    mma16816(c[mi][nj * 2 + 0], af[mi], bf[nj][0], bf[nj][1]);
                    mma16816(c[mi][nj * 2 + 1], af[mi], bf[nj][2], bf[nj][3]);
                }
        }
    };

    load_tiles(0, 0);
    load_tiles(1, 1);
#pragma unroll 1
    for (int kt = 0; kt < NKT_XR; ++kt) {
        if (kt + 1 < NKT_XR) CP_WAIT1(); else CP_WAIT0();
        __syncthreads();
        if (kt + 2 < NKT_XR) load_tiles(kt + 2, (kt + 2) % 3);
        compute(kt % 3);
    }

    float* base = g_outT + (size_t)ib * B_DIM * N_IN;
    const int mrow = b0 + warp_m * 64 + (lane >> 2);
    const int ncol = n0 + warp_n * 32 + (lane & 3) * 2;
#pragma unroll
    for (int mi = 0; mi < 4; ++mi)
#pragma unroll
        for (int n8 = 0; n8 < 4; ++n8) {
            float* p0 = base + (size_t)(mrow + mi * 16) * N_IN + ncol + n8 * 8;
            float* p1 = base + (size_t)(mrow + mi * 16 + 8) * N_IN + ncol + n8 * 8;
            *(float2*)p0 = make_float2(c[mi][n8][0], c[mi][n8][1]);
            *(float2*)p1 = make_float2(c[mi][n8][2], c[mi][n8][3]);
        }
}

// ============================================================================
// buildA fused with normalization:
//   read raw xr planes g_outT[i][b][n], normalize per reference, combine with x,
//   emit A hi/lo: A[bj][b][t*512+n] (t<8: x[t]*xr[bk], t=8: x[bj])
// ============================================================================
__global__ __launch_bounds__(256)
void k_buildA(const float* __restrict__ x, const float* __restrict__ norm_a)
{
    size_t idx = blockIdx.x * 256 + threadIdx.x;    // (b,n)
    int b = (int)(idx >> 9), n = (int)(idx & 511);

    float r8[8];
#pragma unroll
    for (int i = 0; i < 8; ++i)
        r8[i] = g_outT[(size_t)i * BN + idx];

    // grade normalization (norm_a indexed by n, the N_IN dim)
    {
        float n0 = fabsf(r8[0]);
        float n1 = sqrtf(r8[1]*r8[1] + r8[2]*r8[2] + r8[3]*r8[3]);
        float n2 = sqrtf(r8[4]*r8[4] + r8[5]*r8[5] + r8[6]*r8[6]);
        float n3 = fabsf(r8[7]);
        float4 na = *(const float4*)(norm_a + n * 4);
        float s0 = 1.f / (1.f + expf(-na.x));
        float s1 = 1.f / (1.f + expf(-na.y));
        float s2 = 1.f / (1.f + expf(-na.z));
        float s3 = 1.f / (1.f + expf(-na.w));
        float d0 = 1.f / (s0 * (n0 - 1.f) + 1.f + 1e-6f);
        float d1 = 1.f / (s1 * (n1 - 1.f) + 1.f + 1e-6f);
        float d2 = 1.f / (s2 * (n2 - 1.f) + 1.f + 1e-6f);
        float d3 = 1.f / (s3 * (n3 - 1.f) + 1.f + 1e-6f);
        r8[0] *= d0; r8[1] *= d1; r8[2] *= d1; r8[3] *= d1;
        r8[4] *= d2; r8[5] *= d2; r8[6] *= d2; r8[7] *= d3;
    }

    float x8[8];
    *(float4*)(x8)     = *(const float4*)(x + idx * 8);
    *(float4*)(x8 + 4) = *(const float4*)(x + idx * 8 + 4);

#pragma unroll
    for (int bj = 0; bj < 8; ++bj) {
        size_t base = ((size_t)bj * B_DIM + b) * KSL + n;
#pragma unroll
        for (int t = 0; t < 9; ++t) {
            float v;
            if (t < 8) {
                int bk = c_MS[c_MS[t] ^ c_MS[bj]];
                v = x8[t] * r8[bk];
            } else {
                v = x8[bj];
            }
            __nv_bfloat16 hi, lo; bf16_split(v, hi, lo);
            g_Ah[base + (size_t)t * 512] = hi;
            g_Al[base + (size_t)t * 512] = lo;
        }
    }
}

// ============================================================================
// build B (hi/lo bf16): B[bj][m][t*512+n]: t<8 -> sign*weight[m,n,pp(t,bj)]
//                                           t=8 -> w_left[m,n,G[bj]]
// ============================================================================
__global__ __launch_bounds__(256)
void k_buildB(const float* __restrict__ weight, const float* __restrict__ w_left)
{
    size_t idx = blockIdx.x * 256 + threadIdx.x;
    int m = (int)(idx >> 9), n = (int)(idx & 511);
    float w[20], wl[4];
#pragma unroll
    for (int q = 0; q < 5; ++q)
        *(float4*)(w + q * 4) = *(const float4*)(weight + idx * 20 + q * 4);
    *(float4*)(wl) = *(const float4*)(w_left + idx * 4);

#pragma unroll
    for (int bj = 0; bj < 8; ++bj) {
        size_t base = ((size_t)bj * N_OUT + m) * KSL + n;
#pragma unroll
        for (int t = 0; t < 9; ++t) {
            float v;
            if (t < 8) {
                int bk = c_MS[c_MS[t] ^ c_MS[bj]];
                int e = t * 8 + bk;
                v = c_SG[e] ? w[c_P[e]] : -w[c_P[e]];
            } else {
                v = wl[c_G[bj]];
            }
            __nv_bfloat16 hi, lo; bf16_split(v, hi, lo);
            g_Bh[base + (size_t)t * 512] = hi;
            g_Bl[base + (size_t)t * 512] = lo;
        }
    }
}

// ============================================================================
// main GEMM (tensor, bf16x3): g_outT[bj][b][m] = sum_k A[b,k]*B[m,k]
// CTA 128(b) x 128(m), BK=64, 3-stage cp.async, grid (4, 16, 8).
// ============================================================================
__global__ __launch_bounds__(256)
void k_gemm()
{
    extern __shared__ char sm[];
    const uint32_t smb = smem_u32(sm);
    const int tid = threadIdx.x, lane = tid & 31, wid = tid >> 5;
    const int warp_m = wid >> 2, warp_n = wid & 3;
    const int n0 = blockIdx.x * 128, b0 = blockIdx.y * 128;
    const int bj = blockIdx.z;

    const size_t a_row0 = ((size_t)bj * B_DIM + b0) * KSL;
    const size_t b_row0 = ((size_t)bj * N_OUT + n0) * KSL;

    float c[4][4][4];
#pragma unroll
    for (int mi = 0; mi < 4; ++mi)
#pragma unroll
        for (int nn = 0; nn < 4; ++nn)
#pragma unroll
            for (int q = 0; q < 4; ++q) c[mi][nn][q] = 0.f;

    const int ldrow = tid >> 3, ldc16 = tid & 7;
    const uint32_t ld_sw = SWZ(ldrow * 128 + ldc16 * 16);

    const int a_r = warp_m * 64 + (lane & 7) + ((lane >> 3) & 1) * 8;
    const uint32_t a_lin = a_r * 128, a_sw = (a_r & 7) << 4, a_kl = (lane >> 4) * 16;
    const int b_r = warp_n * 32 + (lane & 7) + (lane >> 4) * 8;
    const uint32_t b_lin = b_r * 128, b_sw = (b_r & 7) << 4, b_kl = ((lane >> 3) & 1) * 16;

    auto load_tiles = [&](int kt, int s) {
        const int phase = kt / 72;
        const int kk = kt - phase * 72;
        const __nv_bfloat16* Ap = (phase == 2) ? g_Al : g_Ah;
        const __nv_bfloat16* Bp = (phase == 1) ? g_Bl : g_Bh;
        const uint32_t sA = smb + (uint32_t)s * 32768u;
        const uint32_t sB = sA + 16384u;
#pragma unroll
        for (int j = 0; j < 4; ++j) {
            int row = ldrow + j * 32;
            cp16(sA + ld_sw + j * 4096u, Ap + a_row0 + (size_t)row * KSL + kk * 64 + ldc16 * 8);
            cp16(sB + ld_sw + j * 4096u, Bp + b_row0 + (size_t)row * KSL + kk * 64 + ldc16 * 8);
        }
        CP_COMMIT();
    };

    auto compute = [&](int s) {
        const uint32_t sA = smb + (uint32_t)s * 32768u;
        const uint32_t sB = sA + 16384u;
#pragma unroll
        for (int k16 = 0; k16 < 4; ++k16) {
            uint32_t af[4][4], bf[2][4];
#pragma unroll
            for (int mi = 0; mi < 4; ++mi)
                ldm4(af[mi], sA + a_lin + mi * 2048u + ((k16 * 32u + a_kl) ^ a_sw));
#pragma unroll
            for (int nj = 0; nj < 2; ++nj)
                ldm4(bf[nj], sB + b_lin + nj * 2048u + ((k16 * 32u + b_kl) ^ b_sw));
#pragma unroll
            for (int mi = 0; mi < 4; ++mi)
#pragma unroll
                for (int nj = 0; nj < 2; ++nj) {
                    mma16816(c[mi][nj * 2 + 0], af[mi], bf[nj][0], bf[nj][1]);
                    mma16816(c[mi][nj * 2 + 1], af[mi], bf[nj][2], bf[nj][3]);
                }
        }
    };

    load_tiles(0, 0);
    load_tiles(1, 1);
#pragma unroll 1
    for (int kt = 0; kt < NKT; ++kt) {
        if (kt + 1 < NKT) CP_WAIT1(); else CP_WAIT0();
        __syncthreads();
        if (kt + 2 < NKT) load_tiles(kt + 2, (kt + 2) % 3);
        compute(kt % 3);
    }

    float* base = g_outT + (size_t)bj * B_DIM * N_OUT;
    const int mrow = b0 + warp_m * 64 + (lane >> 2);
    const int ncol = n0 + warp_n * 32 + (lane & 3) * 2;
#pragma unroll
    for (int mi = 0; mi < 4; ++mi)
#pragma unroll
        for (int n8 = 0; n8 < 4; ++n8) {
            float* p0 = base + (size_t)(mrow + mi * 16) * N_OUT + ncol + n8 * 8;
            float* p1 = base + (size_t)(mrow + mi * 16 + 8) * N_OUT + ncol + n8 * 8;
            *(float2*)p0 = make_float2(c[mi][n8][0], c[mi][n8][1]);
            *(float2*)p1 = make_float2(c[mi][n8][2], c[mi][n8][3]);
        }
}

// ============================================================================
// merge: out[b][m][bj] = (g_outT[bj][b][m] + (bj==0)*b_left[m]) * RSQRT2
// ============================================================================
__global__ __launch_bounds__(256)
void k_merge(const float* __restrict__ b_left, float* __restrict__ out)
{
    size_t idx = blockIdx.x * 256 + threadIdx.x;
    int m = (int)(idx & 511);
    float v[8];
#pragma unroll
    for (int bj = 0; bj < 8; ++bj)
        v[bj] = g_outT[(size_t)bj * B_DIM * N_OUT + idx];
    v[0] += b_left[m];
    float* dst = out + idx * 8;
    *(float4*)(dst)     = make_float4(v[0]*RSQRT2, v[1]*RSQRT2, v[2]*RSQRT2, v[3]*RSQRT2);
    *(float4*)(dst + 4) = make_float4(v[4]*RSQRT2, v[5]*RSQRT2, v[6]*RSQRT2, v[7]*RSQRT2);
}

// ============================================================================
extern "C" void kernel_launch(void* const* d_in, const int* in_sizes, int n_in,
                              void* d_out, int out_size) {
    const float* x       = (const float*)d_in[0];
    const float* weight  = (const float*)d_in[1];
    const float* w_right = (const float*)d_in[2];
    const float* w_left  = (const float*)d_in[3];
    const float* b_left  = (const float*)d_in[4];
    const float* norm_a  = (const float*)d_in[5];
    float* out = (float*)d_out;

    cudaFuncSetAttribute(k_gemm,    cudaFuncAttributeMaxDynamicSharedMemorySize, 98304);
    cudaFuncSetAttribute(k_gemm_xr, cudaFuncAttributeMaxDynamicSharedMemorySize, 98304);

    k_splitX<<<(int)(BN / 256), 256>>>(x);
    k_splitW<<<(N_IN * N_IN) / 256, 256>>>(w_right);
    dim3 gx(N_IN / 128, B_DIM / 128, 8);
    k_gemm_xr<<<gx, 256, 98304>>>();
    k_buildA<<<(int)(BN / 256), 256>>>(x, norm_a);
    k_buildB<<<(N_OUT * N_IN) / 256, 256>>>(weight, w_left);
    dim3 gg(N_OUT / 128, B_DIM / 128, 8);
    k_gemm<<<gg, 256, 98304>>>();
    k_merge<<<(B_DIM * N_OUT) / 256, 256>>>(b_left, out);
}

// round 10
// speedup vs baseline: 3.4137x; 1.0758x over previous
#include <cuda_runtime.h>
#include <cuda_bf16.h>
#include <math.h>
#include <stdint.h>

#define B_DIM 2048
#define N_IN  512
#define N_OUT 512
#define RSQRT2 0.70710678118654752440f
#define KSL   4608           // 9 * 512, K per phase (main GEMM)
#define NKT   216            // 3 phases * 72 k-tiles of 64
#define NKT_XR 24            // 3 phases * 8 k-tiles of 64
#define BN    ((size_t)B_DIM * N_IN)

// ---------------- device scratch (static globals; no runtime alloc) --------
__device__ __nv_bfloat16 g_Ah[(size_t)8 * B_DIM * KSL];           // 151 MB
__device__ __nv_bfloat16 g_Al[(size_t)8 * B_DIM * KSL];           // 151 MB
__device__ __nv_bfloat16 g_Bh[(size_t)8 * N_OUT * KSL];           // 37.7 MB
__device__ __nv_bfloat16 g_Bl[(size_t)8 * N_OUT * KSL];           // 37.7 MB
__device__ float g_outT[(size_t)8 * B_DIM * N_OUT];               // 33.5 MB (xr planes, then out planes)
__device__ __nv_bfloat16 g_xh[(size_t)8 * BN];                    // 16.8 MB
__device__ __nv_bfloat16 g_xl[(size_t)8 * BN];                    // 16.8 MB
__device__ __nv_bfloat16 g_wrh[(size_t)4 * N_IN * N_IN];          // 2.1 MB
__device__ __nv_bfloat16 g_wrl[(size_t)4 * N_IN * N_IN];          // 2.1 MB

// ---- Cl(3,0) tables: blades 0:1 1:e1 2:e2 3:e3 4:e12 5:e13 6:e23 7:e123 --
__device__ constexpr int c_P[64] = {
     0, 1, 1, 1, 2, 2, 2, 3,
     5, 4, 7, 7, 6, 6, 9, 8,
     5, 7, 4, 7, 6, 9, 6, 8,
     5, 7, 7, 4, 9, 6, 6, 8,
    13,11,11,15,10,14,14,12,
    13,11,15,11,14,10,14,12,
    13,15,11,11,14,14,10,12,
    19,18,18,18,17,17,17,16};
__device__ constexpr int c_SG[64] = {
    1,1,1,1,1,1,1,1,
    1,1,1,1,1,1,1,1,
    1,0,1,1,0,0,1,0,
    1,0,0,1,1,0,0,1,
    1,0,1,1,0,0,1,0,
    1,0,0,1,1,0,0,1,
    1,1,0,1,0,1,0,0,
    1,1,0,1,0,1,0,0};
__device__ constexpr int c_G[8]  = {0,1,1,1,2,2,2,3};
__device__ constexpr int c_MS[8] = {0,1,2,4,3,5,6,7};

// ---------------- helpers ---------------------------------------------------
__device__ __forceinline__ uint32_t smem_u32(const void* p) {
    uint32_t a;
    asm("{ .reg .u64 t; cvta.to.shared.u64 t, %1; cvt.u32.u64 %0, t; }" : "=r"(a) : "l"(p));
    return a;
}
#define SWZ(o) ((o) ^ (((o) >> 3) & 0x70))

__device__ __forceinline__ void ldm4(uint32_t* r, uint32_t addr) {
    asm volatile("ldmatrix.sync.aligned.m8n8.x4.shared.b16 {%0,%1,%2,%3}, [%4];"
        : "=r"(r[0]), "=r"(r[1]), "=r"(r[2]), "=r"(r[3]) : "r"(addr));
}
__device__ __forceinline__ void mma16816(float* c, const uint32_t* a, uint32_t b0, uint32_t b1) {
    asm volatile(
        "mma.sync.aligned.m16n8k16.row.col.f32.bf16.bf16.f32 "
        "{%0,%1,%2,%3}, {%4,%5,%6,%7}, {%8,%9}, {%0,%1,%2,%3};"
        : "+f"(c[0]), "+f"(c[1]), "+f"(c[2]), "+f"(c[3])
        : "r"(a[0]), "r"(a[1]), "r"(a[2]), "r"(a[3]), "r"(b0), "r"(b1));
}
__device__ __forceinline__ void cp16(uint32_t d, const void* g) {
    asm volatile("cp.async.cg.shared.global [%0], [%1], 16;" :: "r"(d), "l"(g));
}
#define CP_COMMIT() asm volatile("cp.async.commit_group;")
#define CP_WAIT1()  asm volatile("cp.async.wait_group 1;")
#define CP_WAIT0()  asm volatile("cp.async.wait_group 0;")

__device__ __forceinline__ void bf16_split(float v, __nv_bfloat16& hi, __nv_bfloat16& lo) {
    hi = __float2bfloat16(v);
    lo = __float2bfloat16(v - __bfloat162float(hi));
}

// ============================================================================
// splitX: x[b,n,8] -> g_xh/g_xl planes [i][b][n] (bf16 hi/lo)
// ============================================================================
__global__ __launch_bounds__(256)
void k_splitX(const float* __restrict__ x)
{
    size_t idx = blockIdx.x * 256 + threadIdx.x;    // (b,n)
    float x8[8];
    *(float4*)(x8)     = *(const float4*)(x + idx * 8);
    *(float4*)(x8 + 4) = *(const float4*)(x + idx * 8 + 4);
#pragma unroll
    for (int i = 0; i < 8; ++i) {
        __nv_bfloat16 hi, lo; bf16_split(x8[i], hi, lo);
        g_xh[(size_t)i * BN + idx] = hi;
        g_xl[(size_t)i * BN + idx] = lo;
    }
}

// ============================================================================
// splitW: w_right[m,n,4] -> g_wrh/g_wrl planes [g][m][n]
// ============================================================================
__global__ __launch_bounds__(256)
void k_splitW(const float* __restrict__ w_right)
{
    size_t idx = blockIdx.x * 256 + threadIdx.x;    // (m,n)
    float4 w = *(const float4*)(w_right + idx * 4);
    float w4[4] = {w.x, w.y, w.z, w.w};
#pragma unroll
    for (int g = 0; g < 4; ++g) {
        __nv_bfloat16 hi, lo; bf16_split(w4[g], hi, lo);
        g_wrh[(size_t)g * N_IN * N_IN + idx] = hi;
        g_wrl[(size_t)g * N_IN * N_IN + idx] = lo;
    }
}

// ============================================================================
// Shared GEMM core: 128(b) x 128(m) CTA tile, 4 warps of 64x64, BK=64,
// 3-stage cp.async pipeline, single __syncthreads per k-iter, 128 threads.
// smem: 3 stages x (A 16KB + B 16KB) = 96KB dynamic.
// ============================================================================
struct GemmCtx {
    uint32_t smb;
    int lane, warp_m, warp_n;
    int ldrow, ldc16;
    uint32_t ld_sw;
    uint32_t a_lin, a_sw, a_kl;
    uint32_t b_lin, b_sw, b_kl;
    __device__ __forceinline__ void init(int tid) {
        lane = tid & 31;
        int wid = tid >> 5;
        warp_m = wid >> 1; warp_n = wid & 1;
        ldrow = tid >> 3; ldc16 = tid & 7;
        ld_sw = SWZ((uint32_t)(ldrow * 128 + ldc16 * 16));
        int a_r = warp_m * 64 + (lane & 7) + ((lane >> 3) & 1) * 8;
        a_lin = a_r * 128; a_sw = (a_r & 7) << 4; a_kl = (lane >> 4) * 16;
        int b_r = warp_n * 64 + (lane & 7) + (lane >> 4) * 8;
        b_lin = b_r * 128; b_sw = (b_r & 7) << 4; b_kl = ((lane >> 3) & 1) * 16;
    }
};

__device__ __forceinline__ void gemm_load(const GemmCtx& g, int s,
                                          const __nv_bfloat16* Ap, size_t a_row0,
                                          const __nv_bfloat16* Bp, size_t b_row0,
                                          size_t ldk, int kk) {
    const uint32_t sA = g.smb + (uint32_t)s * 32768u;
    const uint32_t sB = sA + 16384u;
#pragma unroll
    for (int j = 0; j < 8; ++j) {
        int row = g.ldrow + j * 16;
        cp16(sA + g.ld_sw + j * 2048u, Ap + a_row0 + (size_t)row * ldk + kk * 64 + g.ldc16 * 8);
        cp16(sB + g.ld_sw + j * 2048u, Bp + b_row0 + (size_t)row * ldk + kk * 64 + g.ldc16 * 8);
    }
    CP_COMMIT();
}

__device__ __forceinline__ void gemm_compute(const GemmCtx& g, int s, float c[4][8][4]) {
    const uint32_t sA = g.smb + (uint32_t)s * 32768u;
    const uint32_t sB = sA + 16384u;
#pragma unroll
    for (int k16 = 0; k16 < 4; ++k16) {
        uint32_t af[4][4], bf[4][4];
#pragma unroll
        for (int mi = 0; mi < 4; ++mi)
            ldm4(af[mi], sA + g.a_lin + mi * 2048u + ((k16 * 32u + g.a_kl) ^ g.a_sw));
#pragma unroll
        for (int nj = 0; nj < 4; ++nj)
            ldm4(bf[nj], sB + g.b_lin + nj * 2048u + ((k16 * 32u + g.b_kl) ^ g.b_sw));
#pragma unroll
        for (int mi = 0; mi < 4; ++mi)
#pragma unroll
            for (int nj = 0; nj < 4; ++nj) {
                mma16816(c[mi][nj * 2 + 0], af[mi], bf[nj][0], bf[nj][1]);
                mma16816(c[mi][nj * 2 + 1], af[mi], bf[nj][2], bf[nj][3]);
            }
    }
}

__device__ __forceinline__ void gemm_store(const GemmCtx& g, float c[4][8][4],
                                           float* base, int b0, int n0, int ldn) {
    const int mrow = b0 + g.warp_m * 64 + (g.lane >> 2);
    const int ncol = n0 + g.warp_n * 64 + (g.lane & 3) * 2;
#pragma unroll
    for (int mi = 0; mi < 4; ++mi)
#pragma unroll
        for (int n8 = 0; n8 < 8; ++n8) {
            float* p0 = base + (size_t)(mrow + mi * 16) * ldn + ncol + n8 * 8;
            float* p1 = base + (size_t)(mrow + mi * 16 + 8) * ldn + ncol + n8 * 8;
            *(float2*)p0 = make_float2(c[mi][n8][0], c[mi][n8][1]);
            *(float2*)p1 = make_float2(c[mi][n8][2], c[mi][n8][3]);
        }
}

// ============================================================================
// xr GEMM (tensor, bf16x3): g_outT[i][b][m] = sum_n x[b,n,i]*w_right[m,n,G[i]]
// grid (4, 16, 8), 128 threads.
// ============================================================================
__global__ __launch_bounds__(128)
void k_gemm_xr()
{
    extern __shared__ char sm[];
    GemmCtx g; g.smb = smem_u32(sm); g.init(threadIdx.x);
    const int n0 = blockIdx.x * 128, b0 = blockIdx.y * 128;
    const int ib = blockIdx.z, gg = c_G[ib];

    const size_t a_row0 = ((size_t)ib * B_DIM + b0) * N_IN;
    const size_t b_row0 = ((size_t)gg * N_IN + n0) * N_IN;

    float c[4][8][4];
#pragma unroll
    for (int mi = 0; mi < 4; ++mi)
#pragma unroll
        for (int nn = 0; nn < 8; ++nn)
#pragma unroll
            for (int q = 0; q < 4; ++q) c[mi][nn][q] = 0.f;

    auto AP = [&](int kt) { int p = kt >> 3; return (p == 2) ? g_xl : g_xh; };
    auto BP = [&](int kt) { int p = kt >> 3; return (p == 1) ? g_wrl : g_wrh; };

    gemm_load(g, 0, AP(0), a_row0, BP(0), b_row0, N_IN, 0);
    gemm_load(g, 1, AP(1), a_row0, BP(1), b_row0, N_IN, 1);
#pragma unroll 1
    for (int kt = 0; kt < NKT_XR; ++kt) {
        if (kt + 1 < NKT_XR) CP_WAIT1(); else CP_WAIT0();
        __syncthreads();
        if (kt + 2 < NKT_XR) {
            int t = kt + 2;
            gemm_load(g, t % 3, AP(t), a_row0, BP(t), b_row0, N_IN, t & 7);
        }
        gemm_compute(g, kt % 3, c);
    }

    gemm_store(g, c, g_outT + (size_t)ib * B_DIM * N_IN, b0, n0, N_IN);
}

// ============================================================================
// buildA fused with normalization:
//   read raw xr planes g_outT[i][b][n], normalize per reference, combine with x,
//   emit A hi/lo: A[bj][b][t*512+n] (t<8: x[t]*xr[bk], t=8: x[bj])
// ============================================================================
__global__ __launch_bounds__(256)
void k_buildA(const float* __restrict__ x, const float* __restrict__ norm_a)
{
    size_t idx = blockIdx.x * 256 + threadIdx.x;    // (b,n)
    int b = (int)(idx >> 9), n = (int)(idx & 511);

    float r8[8];
#pragma unroll
    for (int i = 0; i < 8; ++i)
        r8[i] = g_outT[(size_t)i * BN + idx];

    {
        float n0 = fabsf(r8[0]);
        float n1 = sqrtf(r8[1]*r8[1] + r8[2]*r8[2] + r8[3]*r8[3]);
        float n2 = sqrtf(r8[4]*r8[4] + r8[5]*r8[5] + r8[6]*r8[6]);
        float n3 = fabsf(r8[7]);
        float4 na = *(const float4*)(norm_a + n * 4);
        float s0 = 1.f / (1.f + expf(-na.x));
        float s1 = 1.f / (1.f + expf(-na.y));
        float s2 = 1.f / (1.f + expf(-na.z));
        float s3 = 1.f / (1.f + expf(-na.w));
        float d0 = 1.f / (s0 * (n0 - 1.f) + 1.f + 1e-6f);
        float d1 = 1.f / (s1 * (n1 - 1.f) + 1.f + 1e-6f);
        float d2 = 1.f / (s2 * (n2 - 1.f) + 1.f + 1e-6f);
        float d3 = 1.f / (s3 * (n3 - 1.f) + 1.f + 1e-6f);
        r8[0] *= d0; r8[1] *= d1; r8[2] *= d1; r8[3] *= d1;
        r8[4] *= d2; r8[5] *= d2; r8[6] *= d2; r8[7] *= d3;
    }

    float x8[8];
    *(float4*)(x8)     = *(const float4*)(x + idx * 8);
    *(float4*)(x8 + 4) = *(const float4*)(x + idx * 8 + 4);

#pragma unroll
    for (int bj = 0; bj < 8; ++bj) {
        size_t base = ((size_t)bj * B_DIM + b) * KSL + n;
#pragma unroll
        for (int t = 0; t < 9; ++t) {
            float v;
            if (t < 8) {
                int bk = c_MS[c_MS[t] ^ c_MS[bj]];
                v = x8[t] * r8[bk];
            } else {
                v = x8[bj];
            }
            __nv_bfloat16 hi, lo; bf16_split(v, hi, lo);
            g_Ah[base + (size_t)t * 512] = hi;
            g_Al[base + (size_t)t * 512] = lo;
        }
    }
}

// ============================================================================
// build B (hi/lo bf16): B[bj][m][t*512+n]: t<8 -> sign*weight[m,n,pp(t,bj)]
//                                           t=8 -> w_left[m,n,G[bj]]
// ============================================================================
__global__ __launch_bounds__(256)
void k_buildB(const float* __restrict__ weight, const float* __restrict__ w_left)
{
    size_t idx = blockIdx.x * 256 + threadIdx.x;
    int m = (int)(idx >> 9), n = (int)(idx & 511);
    float w[20], wl[4];
#pragma unroll
    for (int q = 0; q < 5; ++q)
        *(float4*)(w + q * 4) = *(const float4*)(weight + idx * 20 + q * 4);
    *(float4*)(wl) = *(const float4*)(w_left + idx * 4);

#pragma unroll
    for (int bj = 0; bj < 8; ++bj) {
        size_t base = ((size_t)bj * N_OUT + m) * KSL + n;
#pragma unroll
        for (int t = 0; t < 9; ++t) {
            float v;
            if (t < 8) {
                int bk = c_MS[c_MS[t] ^ c_MS[bj]];
                int e = t * 8 + bk;
                v = c_SG[e] ? w[c_P[e]] : -w[c_P[e]];
            } else {
                v = wl[c_G[bj]];
            }
            __nv_bfloat16 hi, lo; bf16_split(v, hi, lo);
            g_Bh[base + (size_t)t * 512] = hi;
            g_Bl[base + (size_t)t * 512] = lo;
        }
    }
}

// ============================================================================
// main GEMM (tensor, bf16x3): g_outT[bj][b][m] = sum_k A[b,k]*B[m,k]
// grid (4, 16, 8), 128 threads.
// ============================================================================
__global__ __launch_bounds__(128)
void k_gemm()
{
    extern __shared__ char sm[];
    GemmCtx g; g.smb = smem_u32(sm); g.init(threadIdx.x);
    const int n0 = blockIdx.x * 128, b0 = blockIdx.y * 128;
    const int bj = blockIdx.z;

    const size_t a_row0 = ((size_t)bj * B_DIM + b0) * KSL;
    const size_t b_row0 = ((size_t)bj * N_OUT + n0) * KSL;

    float c[4][8][4];
#pragma unroll
    for (int mi = 0; mi < 4; ++mi)
#pragma unroll
        for (int nn = 0; nn < 8; ++nn)
#pragma unroll
            for (int q = 0; q < 4; ++q) c[mi][nn][q] = 0.f;

    auto AP = [&](int kt) { int p = kt / 72; return (p == 2) ? g_Al : g_Ah; };
    auto BP = [&](int kt) { int p = kt / 72; return (p == 1) ? g_Bl : g_Bh; };
    auto KK = [&](int kt) { int p = kt / 72; return kt - p * 72; };

    gemm_load(g, 0, AP(0), a_row0, BP(0), b_row0, KSL, KK(0));
    gemm_load(g, 1, AP(1), a_row0, BP(1), b_row0, KSL, KK(1));
#pragma unroll 1
    for (int kt = 0; kt < NKT; ++kt) {
        if (kt + 1 < NKT) CP_WAIT1(); else CP_WAIT0();
        __syncthreads();
        if (kt + 2 < NKT) {
            int t = kt + 2;
            gemm_load(g, t % 3, AP(t), a_row0, BP(t), b_row0, KSL, KK(t));
        }
        gemm_compute(g, kt % 3, c);
    }

    gemm_store(g, c, g_outT + (size_t)bj * B_DIM * N_OUT, b0, n0, N_OUT);
}

// ============================================================================
// merge: out[b][m][bj] = (g_outT[bj][b][m] + (bj==0)*b_left[m]) * RSQRT2
// ============================================================================
__global__ __launch_bounds__(256)
void k_merge(const float* __restrict__ b_left, float* __restrict__ out)
{
    size_t idx = blockIdx.x * 256 + threadIdx.x;
    int m = (int)(idx & 511);
    float v[8];
#pragma unroll
    for (int bj = 0; bj < 8; ++bj)
        v[bj] = g_outT[(size_t)bj * B_DIM * N_OUT + idx];
    v[0] += b_left[m];
    float* dst = out + idx * 8;
    *(float4*)(dst)     = make_float4(v[0]*RSQRT2, v[1]*RSQRT2, v[2]*RSQRT2, v[3]*RSQRT2);
    *(float4*)(dst + 4) = make_float4(v[4]*RSQRT2, v[5]*RSQRT2, v[6]*RSQRT2, v[7]*RSQRT2);
}

// ============================================================================
extern "C" void kernel_launch(void* const* d_in, const int* in_sizes, int n_in,
                              void* d_out, int out_size) {
    const float* x       = (const float*)d_in[0];
    const float* weight  = (const float*)d_in[1];
    const float* w_right = (const float*)d_in[2];
    const float* w_left  = (const float*)d_in[3];
    const float* b_left  = (const float*)d_in[4];
    const float* norm_a  = (const float*)d_in[5];
    float* out = (float*)d_out;

    cudaFuncSetAttribute(k_gemm,    cudaFuncAttributeMaxDynamicSharedMemorySize, 98304);
    cudaFuncSetAttribute(k_gemm_xr, cudaFuncAttributeMaxDynamicSharedMemorySize, 98304);

    k_splitX<<<(int)(BN / 256), 256>>>(x);
    k_splitW<<<(N_IN * N_IN) / 256, 256>>>(w_right);
    dim3 gx(N_IN / 128, B_DIM / 128, 8);
    k_gemm_xr<<<gx, 128, 98304>>>();
    k_buildA<<<(int)(BN / 256), 256>>>(x, norm_a);
    k_buildB<<<(N_OUT * N_IN) / 256, 256>>>(weight, w_left);
    dim3 gg(N_OUT / 128, B_DIM / 128, 8);
    k_gemm<<<gg, 128, 98304>>>();
    k_merge<<<(B_DIM * N_OUT) / 256, 256>>>(b_left, out);
}

// round 11
// speedup vs baseline: 7.3861x; 2.1637x over previous
#include <cuda_runtime.h>
#include <cuda_bf16.h>
#include <cuda_fp16.h>
#include <math.h>
#include <stdint.h>

#define B_DIM 2048
#define N_IN  512
#define N_OUT 512
#define RSQRT2 0.70710678118654752440f
#define KSL   4608           // 9 * 512, K of main GEMM (single fp16 pass)
#define NKT   72             // 72 k-tiles of 64
#define NKT_XR 24            // xr GEMM: 3 bf16 phases * 8 k-tiles of 64
#define BN    ((size_t)B_DIM * N_IN)

// ---------------- device scratch (static globals; no runtime alloc) --------
__device__ __half g_A[(size_t)8 * B_DIM * KSL];                   // 151 MB (fp16)
__device__ __half g_B[(size_t)8 * N_OUT * KSL];                   // 37.7 MB (fp16)
__device__ float g_outT[(size_t)8 * B_DIM * N_OUT];               // 33.5 MB (xr planes, then out planes)
__device__ __nv_bfloat16 g_xh[(size_t)8 * BN];                    // 16.8 MB
__device__ __nv_bfloat16 g_xl[(size_t)8 * BN];                    // 16.8 MB
__device__ __nv_bfloat16 g_wrh[(size_t)4 * N_IN * N_IN];          // 2.1 MB
__device__ __nv_bfloat16 g_wrl[(size_t)4 * N_IN * N_IN];          // 2.1 MB

// ---- Cl(3,0) tables: blades 0:1 1:e1 2:e2 3:e3 4:e12 5:e13 6:e23 7:e123 --
__device__ constexpr int c_P[64] = {
     0, 1, 1, 1, 2, 2, 2, 3,
     5, 4, 7, 7, 6, 6, 9, 8,
     5, 7, 4, 7, 6, 9, 6, 8,
     5, 7, 7, 4, 9, 6, 6, 8,
    13,11,11,15,10,14,14,12,
    13,11,15,11,14,10,14,12,
    13,15,11,11,14,14,10,12,
    19,18,18,18,17,17,17,16};
__device__ constexpr int c_SG[64] = {
    1,1,1,1,1,1,1,1,
    1,1,1,1,1,1,1,1,
    1,0,1,1,0,0,1,0,
    1,0,0,1,1,0,0,1,
    1,0,1,1,0,0,1,0,
    1,0,0,1,1,0,0,1,
    1,1,0,1,0,1,0,0,
    1,1,0,1,0,1,0,0};
__device__ constexpr int c_G[8]  = {0,1,1,1,2,2,2,3};
__device__ constexpr int c_MS[8] = {0,1,2,4,3,5,6,7};

// ---------------- helpers ---------------------------------------------------
__device__ __forceinline__ uint32_t smem_u32(const void* p) {
    uint32_t a;
    asm("{ .reg .u64 t; cvta.to.shared.u64 t, %1; cvt.u32.u64 %0, t; }" : "=r"(a) : "l"(p));
    return a;
}
#define SWZ(o) ((o) ^ (((o) >> 3) & 0x70))

__device__ __forceinline__ void ldm4(uint32_t* r, uint32_t addr) {
    asm volatile("ldmatrix.sync.aligned.m8n8.x4.shared.b16 {%0,%1,%2,%3}, [%4];"
        : "=r"(r[0]), "=r"(r[1]), "=r"(r[2]), "=r"(r[3]) : "r"(addr));
}
__device__ __forceinline__ void mma_bf16(float* c, const uint32_t* a, uint32_t b0, uint32_t b1) {
    asm volatile(
        "mma.sync.aligned.m16n8k16.row.col.f32.bf16.bf16.f32 "
        "{%0,%1,%2,%3}, {%4,%5,%6,%7}, {%8,%9}, {%0,%1,%2,%3};"
        : "+f"(c[0]), "+f"(c[1]), "+f"(c[2]), "+f"(c[3])
        : "r"(a[0]), "r"(a[1]), "r"(a[2]), "r"(a[3]), "r"(b0), "r"(b1));
}
__device__ __forceinline__ void mma_f16(float* c, const uint32_t* a, uint32_t b0, uint32_t b1) {
    asm volatile(
        "mma.sync.aligned.m16n8k16.row.col.f32.f16.f16.f32 "
        "{%0,%1,%2,%3}, {%4,%5,%6,%7}, {%8,%9}, {%0,%1,%2,%3};"
        : "+f"(c[0]), "+f"(c[1]), "+f"(c[2]), "+f"(c[3])
        : "r"(a[0]), "r"(a[1]), "r"(a[2]), "r"(a[3]), "r"(b0), "r"(b1));
}
__device__ __forceinline__ void cp16(uint32_t d, const void* g) {
    asm volatile("cp.async.cg.shared.global [%0], [%1], 16;" :: "r"(d), "l"(g));
}
#define CP_COMMIT() asm volatile("cp.async.commit_group;")
#define CP_WAIT1()  asm volatile("cp.async.wait_group 1;")
#define CP_WAIT0()  asm volatile("cp.async.wait_group 0;")

__device__ __forceinline__ void bf16_split(float v, __nv_bfloat16& hi, __nv_bfloat16& lo) {
    hi = __float2bfloat16(v);
    lo = __float2bfloat16(v - __bfloat162float(hi));
}

// ============================================================================
// splitX: x[b,n,8] -> g_xh/g_xl planes [i][b][n] (bf16 hi/lo)
// ============================================================================
__global__ __launch_bounds__(256)
void k_splitX(const float* __restrict__ x)
{
    size_t idx = blockIdx.x * 256 + threadIdx.x;    // (b,n)
    float x8[8];
    *(float4*)(x8)     = *(const float4*)(x + idx * 8);
    *(float4*)(x8 + 4) = *(const float4*)(x + idx * 8 + 4);
#pragma unroll
    for (int i = 0; i < 8; ++i) {
        __nv_bfloat16 hi, lo; bf16_split(x8[i], hi, lo);
        g_xh[(size_t)i * BN + idx] = hi;
        g_xl[(size_t)i * BN + idx] = lo;
    }
}

// ============================================================================
// splitW: w_right[m,n,4] -> g_wrh/g_wrl planes [g][m][n]
// ============================================================================
__global__ __launch_bounds__(256)
void k_splitW(const float* __restrict__ w_right)
{
    size_t idx = blockIdx.x * 256 + threadIdx.x;    // (m,n)
    float4 w = *(const float4*)(w_right + idx * 4);
    float w4[4] = {w.x, w.y, w.z, w.w};
#pragma unroll
    for (int g = 0; g < 4; ++g) {
        __nv_bfloat16 hi, lo; bf16_split(w4[g], hi, lo);
        g_wrh[(size_t)g * N_IN * N_IN + idx] = hi;
        g_wrl[(size_t)g * N_IN * N_IN + idx] = lo;
    }
}

// ============================================================================
// Shared GEMM core: 128(b) x 128(m) CTA tile, 4 warps of 64x64, BK=64,
// 3-stage cp.async pipeline, single __syncthreads per k-iter, 128 threads.
// smem: 3 stages x (A 16KB + B 16KB) = 96KB dynamic.
// ============================================================================
struct GemmCtx {
    uint32_t smb;
    int lane, warp_m, warp_n;
    int ldrow, ldc16;
    uint32_t ld_sw;
    uint32_t a_lin, a_sw, a_kl;
    uint32_t b_lin, b_sw, b_kl;
    __device__ __forceinline__ void init(int tid) {
        lane = tid & 31;
        int wid = tid >> 5;
        warp_m = wid >> 1; warp_n = wid & 1;
        ldrow = tid >> 3; ldc16 = tid & 7;
        ld_sw = SWZ((uint32_t)(ldrow * 128 + ldc16 * 16));
        int a_r = warp_m * 64 + (lane & 7) + ((lane >> 3) & 1) * 8;
        a_lin = a_r * 128; a_sw = (a_r & 7) << 4; a_kl = (lane >> 4) * 16;
        int b_r = warp_n * 64 + (lane & 7) + (lane >> 4) * 8;
        b_lin = b_r * 128; b_sw = (b_r & 7) << 4; b_kl = ((lane >> 3) & 1) * 16;
    }
};

template <typename T>
__device__ __forceinline__ void gemm_load(const GemmCtx& g, int s,
                                          const T* Ap, size_t a_row0,
                                          const T* Bp, size_t b_row0,
                                          size_t ldk, int kk) {
    const uint32_t sA = g.smb + (uint32_t)s * 32768u;
    const uint32_t sB = sA + 16384u;
#pragma unroll
    for (int j = 0; j < 8; ++j) {
        int row = g.ldrow + j * 16;
        cp16(sA + g.ld_sw + j * 2048u, Ap + a_row0 + (size_t)row * ldk + kk * 64 + g.ldc16 * 8);
        cp16(sB + g.ld_sw + j * 2048u, Bp + b_row0 + (size_t)row * ldk + kk * 64 + g.ldc16 * 8);
    }
    CP_COMMIT();
}

template <bool F16>
__device__ __forceinline__ void gemm_compute(const GemmCtx& g, int s, float c[4][8][4]) {
    const uint32_t sA = g.smb + (uint32_t)s * 32768u;
    const uint32_t sB = sA + 16384u;
#pragma unroll
    for (int k16 = 0; k16 < 4; ++k16) {
        uint32_t af[4][4], bf[4][4];
#pragma unroll
        for (int mi = 0; mi < 4; ++mi)
            ldm4(af[mi], sA + g.a_lin + mi * 2048u + ((k16 * 32u + g.a_kl) ^ g.a_sw));
#pragma unroll
        for (int nj = 0; nj < 4; ++nj)
            ldm4(bf[nj], sB + g.b_lin + nj * 2048u + ((k16 * 32u + g.b_kl) ^ g.b_sw));
#pragma unroll
        for (int mi = 0; mi < 4; ++mi)
#pragma unroll
            for (int nj = 0; nj < 4; ++nj) {
                if (F16) {
                    mma_f16(c[mi][nj * 2 + 0], af[mi], bf[nj][0], bf[nj][1]);
                    mma_f16(c[mi][nj * 2 + 1], af[mi], bf[nj][2], bf[nj][3]);
                } else {
                    mma_bf16(c[mi][nj * 2 + 0], af[mi], bf[nj][0], bf[nj][1]);
                    mma_bf16(c[mi][nj * 2 + 1], af[mi], bf[nj][2], bf[nj][3]);
                }
            }
    }
}

__device__ __forceinline__ void gemm_store(const GemmCtx& g, float c[4][8][4],
                                           float* base, int b0, int n0, int ldn) {
    const int mrow = b0 + g.warp_m * 64 + (g.lane >> 2);
    const int ncol = n0 + g.warp_n * 64 + (g.lane & 3) * 2;
#pragma unroll
    for (int mi = 0; mi < 4; ++mi)
#pragma unroll
        for (int n8 = 0; n8 < 8; ++n8) {
            float* p0 = base + (size_t)(mrow + mi * 16) * ldn + ncol + n8 * 8;
            float* p1 = base + (size_t)(mrow + mi * 16 + 8) * ldn + ncol + n8 * 8;
            *(float2*)p0 = make_float2(c[mi][n8][0], c[mi][n8][1]);
            *(float2*)p1 = make_float2(c[mi][n8][2], c[mi][n8][3]);
        }
}

// ============================================================================
// xr GEMM (tensor, bf16x3): g_outT[i][b][m] = sum_n x[b,n,i]*w_right[m,n,G[i]]
// grid (4, 16, 8), 128 threads.
// ============================================================================
__global__ __launch_bounds__(128)
void k_gemm_xr()
{
    extern __shared__ char sm[];
    GemmCtx g; g.smb = smem_u32(sm); g.init(threadIdx.x);
    const int n0 = blockIdx.x * 128, b0 = blockIdx.y * 128;
    const int ib = blockIdx.z, gg = c_G[ib];

    const size_t a_row0 = ((size_t)ib * B_DIM + b0) * N_IN;
    const size_t b_row0 = ((size_t)gg * N_IN + n0) * N_IN;

    float c[4][8][4];
#pragma unroll
    for (int mi = 0; mi < 4; ++mi)
#pragma unroll
        for (int nn = 0; nn < 8; ++nn)
#pragma unroll
            for (int q = 0; q < 4; ++q) c[mi][nn][q] = 0.f;

    auto AP = [&](int kt) { int p = kt >> 3; return (p == 2) ? g_xl : g_xh; };
    auto BP = [&](int kt) { int p = kt >> 3; return (p == 1) ? g_wrl : g_wrh; };

    gemm_load(g, 0, AP(0), a_row0, BP(0), b_row0, (size_t)N_IN, 0);
    gemm_load(g, 1, AP(1), a_row0, BP(1), b_row0, (size_t)N_IN, 1);
#pragma unroll 1
    for (int kt = 0; kt < NKT_XR; ++kt) {
        if (kt + 1 < NKT_XR) CP_WAIT1(); else CP_WAIT0();
        __syncthreads();
        if (kt + 2 < NKT_XR) {
            int t = kt + 2;
            gemm_load(g, t % 3, AP(t), a_row0, BP(t), b_row0, (size_t)N_IN, t & 7);
        }
        gemm_compute<false>(g, kt % 3, c);
    }

    gemm_store(g, c, g_outT + (size_t)ib * B_DIM * N_IN, b0, n0, N_IN);
}

// ============================================================================
// buildA fused with normalization:
//   read raw xr planes g_outT[i][b][n], normalize per reference, combine with x,
//   emit A (fp16): A[bj][b][t*512+n] (t<8: x[t]*xr[bk], t=8: x[bj])
// ============================================================================
__global__ __launch_bounds__(256)
void k_buildA(const float* __restrict__ x, const float* __restrict__ norm_a)
{
    size_t idx = blockIdx.x * 256 + threadIdx.x;    // (b,n)
    int b = (int)(idx >> 9), n = (int)(idx & 511);

    float r8[8];
#pragma unroll
    for (int i = 0; i < 8; ++i)
        r8[i] = g_outT[(size_t)i * BN + idx];

    {
        float n0 = fabsf(r8[0]);
        float n1 = sqrtf(r8[1]*r8[1] + r8[2]*r8[2] + r8[3]*r8[3]);
        float n2 = sqrtf(r8[4]*r8[4] + r8[5]*r8[5] + r8[6]*r8[6]);
        float n3 = fabsf(r8[7]);
        float4 na = *(const float4*)(norm_a + n * 4);
        float s0 = 1.f / (1.f + expf(-na.x));
        float s1 = 1.f / (1.f + expf(-na.y));
        float s2 = 1.f / (1.f + expf(-na.z));
        float s3 = 1.f / (1.f + expf(-na.w));
        float d0 = 1.f / (s0 * (n0 - 1.f) + 1.f + 1e-6f);
        float d1 = 1.f / (s1 * (n1 - 1.f) + 1.f + 1e-6f);
        float d2 = 1.f / (s2 * (n2 - 1.f) + 1.f + 1e-6f);
        float d3 = 1.f / (s3 * (n3 - 1.f) + 1.f + 1e-6f);
        r8[0] *= d0; r8[1] *= d1; r8[2] *= d1; r8[3] *= d1;
        r8[4] *= d2; r8[5] *= d2; r8[6] *= d2; r8[7] *= d3;
    }

    float x8[8];
    *(float4*)(x8)     = *(const float4*)(x + idx * 8);
    *(float4*)(x8 + 4) = *(const float4*)(x + idx * 8 + 4);

#pragma unroll
    for (int bj = 0; bj < 8; ++bj) {
        size_t base = ((size_t)bj * B_DIM + b) * KSL + n;
#pragma unroll
        for (int t = 0; t < 9; ++t) {
            float v;
            if (t < 8) {
                int bk = c_MS[c_MS[t] ^ c_MS[bj]];
                v = x8[t] * r8[bk];
            } else {
                v = x8[bj];
            }
            g_A[base + (size_t)t * 512] = __float2half(v);
        }
    }
}

// ============================================================================
// build B (fp16): B[bj][m][t*512+n]: t<8 -> sign*weight[m,n,pp(t,bj)]
//                                     t=8 -> w_left[m,n,G[bj]]
// ============================================================================
__global__ __launch_bounds__(256)
void k_buildB(const float* __restrict__ weight, const float* __restrict__ w_left)
{
    size_t idx = blockIdx.x * 256 + threadIdx.x;
    int m = (int)(idx >> 9), n = (int)(idx & 511);
    float w[20], wl[4];
#pragma unroll
    for (int q = 0; q < 5; ++q)
        *(float4*)(w + q * 4) = *(const float4*)(weight + idx * 20 + q * 4);
    *(float4*)(wl) = *(const float4*)(w_left + idx * 4);

#pragma unroll
    for (int bj = 0; bj < 8; ++bj) {
        size_t base = ((size_t)bj * N_OUT + m) * KSL + n;
#pragma unroll
        for (int t = 0; t < 9; ++t) {
            float v;
            if (t < 8) {
                int bk = c_MS[c_MS[t] ^ c_MS[bj]];
                int e = t * 8 + bk;
                v = c_SG[e] ? w[c_P[e]] : -w[c_P[e]];
            } else {
                v = wl[c_G[bj]];
            }
            g_B[base + (size_t)t * 512] = __float2half(v);
        }
    }
}

// ============================================================================
// main GEMM (tensor, single fp16 pass): g_outT[bj][b][m] = sum_k A[b,k]*B[m,k]
// grid (4, 16, 8), 128 threads, NKT=72.
// ============================================================================
__global__ __launch_bounds__(128)
void k_gemm()
{
    extern __shared__ char sm[];
    GemmCtx g; g.smb = smem_u32(sm); g.init(threadIdx.x);
    const int n0 = blockIdx.x * 128, b0 = blockIdx.y * 128;
    const int bj = blockIdx.z;

    const size_t a_row0 = ((size_t)bj * B_DIM + b0) * KSL;
    const size_t b_row0 = ((size_t)bj * N_OUT + n0) * KSL;

    float c[4][8][4];
#pragma unroll
    for (int mi = 0; mi < 4; ++mi)
#pragma unroll
        for (int nn = 0; nn < 8; ++nn)
#pragma unroll
            for (int q = 0; q < 4; ++q) c[mi][nn][q] = 0.f;

    gemm_load(g, 0, g_A, a_row0, g_B, b_row0, (size_t)KSL, 0);
    gemm_load(g, 1, g_A, a_row0, g_B, b_row0, (size_t)KSL, 1);
#pragma unroll 1
    for (int kt = 0; kt < NKT; ++kt) {
        if (kt + 1 < NKT) CP_WAIT1(); else CP_WAIT0();
        __syncthreads();
        if (kt + 2 < NKT)
            gemm_load(g, (kt + 2) % 3, g_A, a_row0, g_B, b_row0, (size_t)KSL, kt + 2);
        gemm_compute<true>(g, kt % 3, c);
    }

    gemm_store(g, c, g_outT + (size_t)bj * B_DIM * N_OUT, b0, n0, N_OUT);
}

// ============================================================================
// merge: out[b][m][bj] = (g_outT[bj][b][m] + (bj==0)*b_left[m]) * RSQRT2
// ============================================================================
__global__ __launch_bounds__(256)
void k_merge(const float* __restrict__ b_left, float* __restrict__ out)
{
    size_t idx = blockIdx.x * 256 + threadIdx.x;
    int m = (int)(idx & 511);
    float v[8];
#pragma unroll
    for (int bj = 0; bj < 8; ++bj)
        v[bj] = g_outT[(size_t)bj * B_DIM * N_OUT + idx];
    v[0] += b_left[m];
    float* dst = out + idx * 8;
    *(float4*)(dst)     = make_float4(v[0]*RSQRT2, v[1]*RSQRT2, v[2]*RSQRT2, v[3]*RSQRT2);
    *(float4*)(dst + 4) = make_float4(v[4]*RSQRT2, v[5]*RSQRT2, v[6]*RSQRT2, v[7]*RSQRT2);
}

// ============================================================================
extern "C" void kernel_launch(void* const* d_in, const int* in_sizes, int n_in,
                              void* d_out, int out_size) {
    const float* x       = (const float*)d_in[0];
    const float* weight  = (const float*)d_in[1];
    const float* w_right = (const float*)d_in[2];
    const float* w_left  = (const float*)d_in[3];
    const float* b_left  = (const float*)d_in[4];
    const float* norm_a  = (const float*)d_in[5];
    float* out = (float*)d_out;

    cudaFuncSetAttribute(k_gemm,    cudaFuncAttributeMaxDynamicSharedMemorySize, 98304);
    cudaFuncSetAttribute(k_gemm_xr, cudaFuncAttributeMaxDynamicSharedMemorySize, 98304);

    k_splitX<<<(int)(BN / 256), 256>>>(x);
    k_splitW<<<(N_IN * N_IN) / 256, 256>>>(w_right);
    dim3 gx(N_IN / 128, B_DIM / 128, 8);
    k_gemm_xr<<<gx, 128, 98304>>>();
    k_buildA<<<(int)(BN / 256), 256>>>(x, norm_a);
    k_buildB<<<(N_OUT * N_IN) / 256, 256>>>(weight, w_left);
    dim3 gg(N_OUT / 128, B_DIM / 128, 8);
    k_gemm<<<gg, 128, 98304>>>();
    k_merge<<<(B_DIM * N_OUT) / 256, 256>>>(b_left, out);
}

// round 13
// speedup vs baseline: 8.5106x; 1.1522x over previous
#include <cuda_runtime.h>
#include <cuda_bf16.h>
#include <cuda_fp16.h>
#include <math.h>
#include <stdint.h>

#define B_DIM 2048
#define N_IN  512
#define N_OUT 512
#define RSQRT2 0.70710678118654752440f
#define KSL   4608           // 9 * 512, K of main GEMM (single fp16 pass)
#define NKT   72             // 72 k-tiles of 64
#define NKT_XR 8             // xr GEMM: single fp16 pass, 8 k-tiles of 64
#define BN    ((size_t)B_DIM * N_IN)

// ---------------- device scratch (static globals; no runtime alloc) --------
__device__ __half g_A[(size_t)8 * B_DIM * KSL];                   // 151 MB (fp16)
__device__ __half g_B[(size_t)8 * N_OUT * KSL];                   // 37.7 MB (fp16)
__device__ float g_outT[(size_t)8 * B_DIM * N_OUT];               // 33.5 MB (xr planes, then out planes)
__device__ __half g_xf[(size_t)8 * BN];                           // 8.4 MB (fp16)
__device__ __half g_wrf[(size_t)4 * N_IN * N_IN];                 // 2.1 MB (fp16)

// ---- Cl(3,0) tables: blades 0:1 1:e1 2:e2 3:e3 4:e12 5:e13 6:e23 7:e123 --
__device__ constexpr int c_P[64] = {
     0, 1, 1, 1, 2, 2, 2, 3,
     5, 4, 7, 7, 6, 6, 9, 8,
     5, 7, 4, 7, 6, 9, 6, 8,
     5, 7, 7, 4, 9, 6, 6, 8,
    13,11,11,15,10,14,14,12,
    13,11,15,11,14,10,14,12,
    13,15,11,11,14,14,10,12,
    19,18,18,18,17,17,17,16};
__device__ constexpr int c_SG[64] = {
    1,1,1,1,1,1,1,1,
    1,1,1,1,1,1,1,1,
    1,0,1,1,0,0,1,0,
    1,0,0,1,1,0,0,1,
    1,0,1,1,0,0,1,0,
    1,0,0,1,1,0,0,1,
    1,1,0,1,0,1,0,0,
    1,1,0,1,0,1,0,0};
__device__ constexpr int c_G[8]  = {0,1,1,1,2,2,2,3};
__device__ constexpr int c_MS[8] = {0,1,2,4,3,5,6,7};

// ---------------- helpers ---------------------------------------------------
__device__ __forceinline__ uint32_t smem_u32(const void* p) {
    uint32_t a;
    asm("{ .reg .u64 t; cvta.to.shared.u64 t, %1; cvt.u32.u64 %0, t; }" : "=r"(a) : "l"(p));
    return a;
}
#define SWZ(o) ((o) ^ (((o) >> 3) & 0x70))

__device__ __forceinline__ void ldm4(uint32_t* r, uint32_t addr) {
    asm volatile("ldmatrix.sync.aligned.m8n8.x4.shared.b16 {%0,%1,%2,%3}, [%4];"
        : "=r"(r[0]), "=r"(r[1]), "=r"(r[2]), "=r"(r[3]) : "r"(addr));
}
__device__ __forceinline__ void mma_f16(float* c, const uint32_t* a, uint32_t b0, uint32_t b1) {
    asm volatile(
        "mma.sync.aligned.m16n8k16.row.col.f32.f16.f16.f32 "
        "{%0,%1,%2,%3}, {%4,%5,%6,%7}, {%8,%9}, {%0,%1,%2,%3};"
        : "+f"(c[0]), "+f"(c[1]), "+f"(c[2]), "+f"(c[3])
        : "r"(a[0]), "r"(a[1]), "r"(a[2]), "r"(a[3]), "r"(b0), "r"(b1));
}
__device__ __forceinline__ void cp16(uint32_t d, const void* g) {
    asm volatile("cp.async.cg.shared.global [%0], [%1], 16;" :: "r"(d), "l"(g));
}
#define CP_COMMIT() asm volatile("cp.async.commit_group;")
#define CP_WAIT1()  asm volatile("cp.async.wait_group 1;")
#define CP_WAIT0()  asm volatile("cp.async.wait_group 0;")

// ============================================================================
// splitX: x[b,n,8] -> g_xf planes [i][b][n] (fp16)
// ============================================================================
__global__ __launch_bounds__(256)
void k_splitX(const float* __restrict__ x)
{
    size_t idx = blockIdx.x * 256 + threadIdx.x;    // (b,n)
    float x8[8];
    *(float4*)(x8)     = *(const float4*)(x + idx * 8);
    *(float4*)(x8 + 4) = *(const float4*)(x + idx * 8 + 4);
#pragma unroll
    for (int i = 0; i < 8; ++i)
        g_xf[(size_t)i * BN + idx] = __float2half(x8[i]);
}

// ============================================================================
// splitW: w_right[m,n,4] -> g_wrf planes [g][m][n] (fp16)
// ============================================================================
__global__ __launch_bounds__(256)
void k_splitW(const float* __restrict__ w_right)
{
    size_t idx = blockIdx.x * 256 + threadIdx.x;    // (m,n)
    float4 w = *(const float4*)(w_right + idx * 4);
    float w4[4] = {w.x, w.y, w.z, w.w};
#pragma unroll
    for (int g = 0; g < 4; ++g)
        g_wrf[(size_t)g * N_IN * N_IN + idx] = __float2half(w4[g]);
}

// ============================================================================
// Shared GEMM core: 128(b) x 128(m) CTA tile, 4 warps of 64x64, BK=64,
// 3-stage cp.async pipeline, single __syncthreads per k-iter, 128 threads.
// smem: 3 stages x (A 16KB + B 16KB) = 96KB dynamic.
// ============================================================================
struct GemmCtx {
    uint32_t smb;
    int lane, warp_m, warp_n;
    int ldrow, ldc16;
    uint32_t ld_sw;
    uint32_t a_lin, a_sw, a_kl;
    uint32_t b_lin, b_sw, b_kl;
    __device__ __forceinline__ void init(int tid) {
        lane = tid & 31;
        int wid = tid >> 5;
        warp_m = wid >> 1; warp_n = wid & 1;
        ldrow = tid >> 3; ldc16 = tid & 7;
        ld_sw = SWZ((uint32_t)(ldrow * 128 + ldc16 * 16));
        int a_r = warp_m * 64 + (lane & 7) + ((lane >> 3) & 1) * 8;
        a_lin = a_r * 128; a_sw = (a_r & 7) << 4; a_kl = (lane >> 4) * 16;
        int b_r = warp_n * 64 + (lane & 7) + (lane >> 4) * 8;
        b_lin = b_r * 128; b_sw = (b_r & 7) << 4; b_kl = ((lane >> 3) & 1) * 16;
    }
};

__device__ __forceinline__ void gemm_load(const GemmCtx& g, int s,
                                          const __half* Ap, size_t a_row0,
                                          const __half* Bp, size_t b_row0,
                                          size_t ldk, int kk) {
    const uint32_t sA = g.smb + (uint32_t)s * 32768u;
    const uint32_t sB = sA + 16384u;
#pragma unroll
    for (int j = 0; j < 8; ++j) {
        int row = g.ldrow + j * 16;
        cp16(sA + g.ld_sw + j * 2048u, Ap + a_row0 + (size_t)row * ldk + kk * 64 + g.ldc16 * 8);
        cp16(sB + g.ld_sw + j * 2048u, Bp + b_row0 + (size_t)row * ldk + kk * 64 + g.ldc16 * 8);
    }
    CP_COMMIT();
}

__device__ __forceinline__ void gemm_compute(const GemmCtx& g, int s, float c[4][8][4]) {
    const uint32_t sA = g.smb + (uint32_t)s * 32768u;
    const uint32_t sB = sA + 16384u;
#pragma unroll
    for (int k16 = 0; k16 < 4; ++k16) {
        uint32_t af[4][4], bf[4][4];
#pragma unroll
        for (int mi = 0; mi < 4; ++mi)
            ldm4(af[mi], sA + g.a_lin + mi * 2048u + ((k16 * 32u + g.a_kl) ^ g.a_sw));
#pragma unroll
        for (int nj = 0; nj < 4; ++nj)
            ldm4(bf[nj], sB + g.b_lin + nj * 2048u + ((k16 * 32u + g.b_kl) ^ g.b_sw));
#pragma unroll
        for (int mi = 0; mi < 4; ++mi)
#pragma unroll
            for (int nj = 0; nj < 4; ++nj) {
                mma_f16(c[mi][nj * 2 + 0], af[mi], bf[nj][0], bf[nj][1]);
                mma_f16(c[mi][nj * 2 + 1], af[mi], bf[nj][2], bf[nj][3]);
            }
    }
}

__device__ __forceinline__ void gemm_store(const GemmCtx& g, float c[4][8][4],
                                           float* base, int b0, int n0, int ldn) {
    const int mrow = b0 + g.warp_m * 64 + (g.lane >> 2);
    const int ncol = n0 + g.warp_n * 64 + (g.lane & 3) * 2;
#pragma unroll
    for (int mi = 0; mi < 4; ++mi)
#pragma unroll
        for (int n8 = 0; n8 < 8; ++n8) {
            float* p0 = base + (size_t)(mrow + mi * 16) * ldn + ncol + n8 * 8;
            float* p1 = base + (size_t)(mrow + mi * 16 + 8) * ldn + ncol + n8 * 8;
            *(float2*)p0 = make_float2(c[mi][n8][0], c[mi][n8][1]);
            *(float2*)p1 = make_float2(c[mi][n8][2], c[mi][n8][3]);
        }
}

// ============================================================================
// xr GEMM (tensor, single fp16): g_outT[i][b][m] = sum_n x[b,n,i]*w_right[m,n,G[i]]
// grid (4, 16, 8), 128 threads.
// ============================================================================
__global__ __launch_bounds__(128)
void k_gemm_xr()
{
    extern __shared__ char sm[];
    GemmCtx g; g.smb = smem_u32(sm); g.init(threadIdx.x);
    const int n0 = blockIdx.x * 128, b0 = blockIdx.y * 128;
    const int ib = blockIdx.z, gg = c_G[ib];

    const size_t a_row0 = ((size_t)ib * B_DIM + b0) * N_IN;
    const size_t b_row0 = ((size_t)gg * N_IN + n0) * N_IN;

    float c[4][8][4];
#pragma unroll
    for (int mi = 0; mi < 4; ++mi)
#pragma unroll
        for (int nn = 0; nn < 8; ++nn)
#pragma unroll
            for (int q = 0; q < 4; ++q) c[mi][nn][q] = 0.f;

    gemm_load(g, 0, g_xf, a_row0, g_wrf, b_row0, (size_t)N_IN, 0);
    gemm_load(g, 1, g_xf, a_row0, g_wrf, b_row0, (size_t)N_IN, 1);
#pragma unroll 1
    for (int kt = 0; kt < NKT_XR; ++kt) {
        if (kt + 1 < NKT_XR) CP_WAIT1(); else CP_WAIT0();
        __syncthreads();
        if (kt + 2 < NKT_XR)
            gemm_load(g, (kt + 2) % 3, g_xf, a_row0, g_wrf, b_row0, (size_t)N_IN, kt + 2);
        gemm_compute(g, kt % 3, c);
    }

    gemm_store(g, c, g_outT + (size_t)ib * B_DIM * N_IN, b0, n0, N_IN);
}

// ============================================================================
// buildA fused with normalization:
//   read raw xr planes g_outT[i][b][n], normalize per reference, combine with x,
//   emit A (fp16): A[bj][b][t*512+n] (t<8: x[t]*xr[bk], t=8: x[bj])
// ============================================================================
__global__ __launch_bounds__(256)
void k_buildA(const float* __restrict__ x, const float* __restrict__ norm_a)
{
    size_t idx = blockIdx.x * 256 + threadIdx.x;    // (b,n)
    int b = (int)(idx >> 9), n = (int)(idx & 511);

    float r8[8];
#pragma unroll
    for (int i = 0; i < 8; ++i)
        r8[i] = g_outT[(size_t)i * BN + idx];

    {
        float n0 = fabsf(r8[0]);
        float n1 = sqrtf(r8[1]*r8[1] + r8[2]*r8[2] + r8[3]*r8[3]);
        float n2 = sqrtf(r8[4]*r8[4] + r8[5]*r8[5] + r8[6]*r8[6]);
        float n3 = fabsf(r8[7]);
        float4 na = *(const float4*)(norm_a + n * 4);
        float s0 = 1.f / (1.f + expf(-na.x));
        float s1 = 1.f / (1.f + expf(-na.y));
        float s2 = 1.f / (1.f + expf(-na.z));
        float s3 = 1.f / (1.f + expf(-na.w));
        float d0 = 1.f / (s0 * (n0 - 1.f) + 1.f + 1e-6f);
        float d1 = 1.f / (s1 * (n1 - 1.f) + 1.f + 1e-6f);
        float d2 = 1.f / (s2 * (n2 - 1.f) + 1.f + 1e-6f);
        float d3 = 1.f / (s3 * (n3 - 1.f) + 1.f + 1e-6f);
        r8[0] *= d0; r8[1] *= d1; r8[2] *= d1; r8[3] *= d1;
        r8[4] *= d2; r8[5] *= d2; r8[6] *= d2; r8[7] *= d3;
    }

    float x8[8];
    *(float4*)(x8)     = *(const float4*)(x + idx * 8);
    *(float4*)(x8 + 4) = *(const float4*)(x + idx * 8 + 4);

#pragma unroll
    for (int bj = 0; bj < 8; ++bj) {
        size_t base = ((size_t)bj * B_DIM + b) * KSL + n;
#pragma unroll
        for (int t = 0; t < 9; ++t) {
            float v;
            if (t < 8) {
                int bk = c_MS[c_MS[t] ^ c_MS[bj]];
                v = x8[t] * r8[bk];
            } else {
                v = x8[bj];
            }
            g_A[base + (size_t)t * 512] = __float2half(v);
        }
    }
}

// ============================================================================
// build B (fp16): B[bj][m][t*512+n]: t<8 -> sign*weight[m,n,pp(t,bj)]
//                                     t=8 -> w_left[m,n,G[bj]]
// ============================================================================
__global__ __launch_bounds__(256)
void k_buildB(const float* __restrict__ weight, const float* __restrict__ w_left)
{
    size_t idx = blockIdx.x * 256 + threadIdx.x;
    int m = (int)(idx >> 9), n = (int)(idx & 511);
    float w[20], wl[4];
#pragma unroll
    for (int q = 0; q < 5; ++q)
        *(float4*)(w + q * 4) = *(const float4*)(weight + idx * 20 + q * 4);
    *(float4*)(wl) = *(const float4*)(w_left + idx * 4);

#pragma unroll
    for (int bj = 0; bj < 8; ++bj) {
        size_t base = ((size_t)bj * N_OUT + m) * KSL + n;
#pragma unroll
        for (int t = 0; t < 9; ++t) {
            float v;
            if (t < 8) {
                int bk = c_MS[c_MS[t] ^ c_MS[bj]];
                int e = t * 8 + bk;
                v = c_SG[e] ? w[c_P[e]] : -w[c_P[e]];
            } else {
                v = wl[c_G[bj]];
            }
            g_B[base + (size_t)t * 512] = __float2half(v);
        }
    }
}

// ============================================================================
// main GEMM (tensor, single fp16 pass): g_outT[bj][b][m] = sum_k A[b,k]*B[m,k]
// grid (4, 16, 8), 128 threads, NKT=72.
// ============================================================================
__global__ __launch_bounds__(128)
void k_gemm()
{
    extern __shared__ char sm[];
    GemmCtx g; g.smb = smem_u32(sm); g.init(threadIdx.x);
    const int n0 = blockIdx.x * 128, b0 = blockIdx.y * 128;
    const int bj = blockIdx.z;

    const size_t a_row0 = ((size_t)bj * B_DIM + b0) * KSL;
    const size_t b_row0 = ((size_t)bj * N_OUT + n0) * KSL;

    float c[4][8][4];
#pragma unroll
    for (int mi = 0; mi < 4; ++mi)
#pragma unroll
        for (int nn = 0; nn < 8; ++nn)
#pragma unroll
            for (int q = 0; q < 4; ++q) c[mi][nn][q] = 0.f;

    gemm_load(g, 0, g_A, a_row0, g_B, b_row0, (size_t)KSL, 0);
    gemm_load(g, 1, g_A, a_row0, g_B, b_row0, (size_t)KSL, 1);
#pragma unroll 1
    for (int kt = 0; kt < NKT; ++kt) {
        if (kt + 1 < NKT) CP_WAIT1(); else CP_WAIT0();
        __syncthreads();
        if (kt + 2 < NKT)
            gemm_load(g, (kt + 2) % 3, g_A, a_row0, g_B, b_row0, (size_t)KSL, kt + 2);
        gemm_compute(g, kt % 3, c);
    }

    gemm_store(g, c, g_outT + (size_t)bj * B_DIM * N_OUT, b0, n0, N_OUT);
}

// ============================================================================
// merge: out[b][m][bj] = (g_outT[bj][b][m] + (bj==0)*b_left[m]) * RSQRT2
// ============================================================================
__global__ __launch_bounds__(256)
void k_merge(const float* __restrict__ b_left, float* __restrict__ out)
{
    size_t idx = blockIdx.x * 256 + threadIdx.x;
    int m = (int)(idx & 511);
    float v[8];
#pragma unroll
    for (int bj = 0; bj < 8; ++bj)
        v[bj] = g_outT[(size_t)bj * B_DIM * N_OUT + idx];
    v[0] += b_left[m];
    float* dst = out + idx * 8;
    *(float4*)(dst)     = make_float4(v[0]*RSQRT2, v[1]*RSQRT2, v[2]*RSQRT2, v[3]*RSQRT2);
    *(float4*)(dst + 4) = make_float4(v[4]*RSQRT2, v[5]*RSQRT2, v[6]*RSQRT2, v[7]*RSQRT2);
}

// ============================================================================
extern "C" void kernel_launch(void* const* d_in, const int* in_sizes, int n_in,
                              void* d_out, int out_size) {
    const float* x       = (const float*)d_in[0];
    const float* weight  = (const float*)d_in[1];
    const float* w_right = (const float*)d_in[2];
    const float* w_left  = (const float*)d_in[3];
    const float* b_left  = (const float*)d_in[4];
    const float* norm_a  = (const float*)d_in[5];
    float* out = (float*)d_out;

    cudaFuncSetAttribute(k_gemm,    cudaFuncAttributeMaxDynamicSharedMemorySize, 98304);
    cudaFuncSetAttribute(k_gemm_xr, cudaFuncAttributeMaxDynamicSharedMemorySize, 98304);

    k_splitX<<<(int)(BN / 256), 256>>>(x);
    k_splitW<<<(N_IN * N_IN) / 256, 256>>>(w_right);
    dim3 gx(N_IN / 128, B_DIM / 128, 8);
    k_gemm_xr<<<gx, 128, 98304>>>();
    k_buildA<<<(int)(BN / 256), 256>>>(x, norm_a);
    k_buildB<<<(N_OUT * N_IN) / 256, 256>>>(weight, w_left);
    dim3 gg(N_OUT / 128, B_DIM / 128, 8);
    k_gemm<<<gg, 128, 98304>>>();
    k_merge<<<(B_DIM * N_OUT) / 256, 256>>>(b_left, out);
}

// round 14
// speedup vs baseline: 8.5178x; 1.0008x over previous
#include <cuda_runtime.h>
#include <cuda_bf16.h>
#include <cuda_fp16.h>
#include <math.h>
#include <stdint.h>

#define B_DIM 2048
#define N_IN  512
#define N_OUT 512
#define RSQRT2 0.70710678118654752440f
#define KSL   4608           // 9 * 512, K of main GEMM (single fp16 pass)
#define NKT   72             // 72 k-tiles of 64
#define NKT_XR 8             // xr GEMM: single fp16 pass, 8 k-tiles of 64
#define BN    ((size_t)B_DIM * N_IN)

// ---------------- device scratch (static globals; no runtime alloc) --------
__device__ __half g_A[(size_t)8 * B_DIM * KSL];                   // 151 MB (fp16)
__device__ __half g_B[(size_t)8 * N_OUT * KSL];                   // 37.7 MB (fp16)
__device__ float g_outT[(size_t)8 * B_DIM * N_OUT];               // 33.5 MB (xr planes, then out planes)
__device__ __half g_xf[(size_t)8 * BN];                           // 8.4 MB (fp16)
__device__ __half g_wrf[(size_t)4 * N_IN * N_IN];                 // 2.1 MB (fp16)

// ---- Cl(3,0) tables: blades 0:1 1:e1 2:e2 3:e3 4:e12 5:e13 6:e23 7:e123 --
__device__ constexpr int c_P[64] = {
     0, 1, 1, 1, 2, 2, 2, 3,
     5, 4, 7, 7, 6, 6, 9, 8,
     5, 7, 4, 7, 6, 9, 6, 8,
     5, 7, 7, 4, 9, 6, 6, 8,
    13,11,11,15,10,14,14,12,
    13,11,15,11,14,10,14,12,
    13,15,11,11,14,14,10,12,
    19,18,18,18,17,17,17,16};
__device__ constexpr int c_SG[64] = {
    1,1,1,1,1,1,1,1,
    1,1,1,1,1,1,1,1,
    1,0,1,1,0,0,1,0,
    1,0,0,1,1,0,0,1,
    1,0,1,1,0,0,1,0,
    1,0,0,1,1,0,0,1,
    1,1,0,1,0,1,0,0,
    1,1,0,1,0,1,0,0};
__device__ constexpr int c_G[8]  = {0,1,1,1,2,2,2,3};
__device__ constexpr int c_MS[8] = {0,1,2,4,3,5,6,7};

// ---------------- helpers ---------------------------------------------------
__device__ __forceinline__ uint32_t smem_u32(const void* p) {
    uint32_t a;
    asm("{ .reg .u64 t; cvta.to.shared.u64 t, %1; cvt.u32.u64 %0, t; }" : "=r"(a) : "l"(p));
    return a;
}
#define SWZ(o) ((o) ^ (((o) >> 3) & 0x70))

__device__ __forceinline__ void ldm4(uint32_t* r, uint32_t addr) {
    asm volatile("ldmatrix.sync.aligned.m8n8.x4.shared.b16 {%0,%1,%2,%3}, [%4];"
        : "=r"(r[0]), "=r"(r[1]), "=r"(r[2]), "=r"(r[3]) : "r"(addr));
}
__device__ __forceinline__ void mma_f16(float* c, const uint32_t* a, uint32_t b0, uint32_t b1) {
    asm volatile(
        "mma.sync.aligned.m16n8k16.row.col.f32.f16.f16.f32 "
        "{%0,%1,%2,%3}, {%4,%5,%6,%7}, {%8,%9}, {%0,%1,%2,%3};"
        : "+f"(c[0]), "+f"(c[1]), "+f"(c[2]), "+f"(c[3])
        : "r"(a[0]), "r"(a[1]), "r"(a[2]), "r"(a[3]), "r"(b0), "r"(b1));
}
__device__ __forceinline__ void cp16(uint32_t d, const void* g) {
    asm volatile("cp.async.cg.shared.global [%0], [%1], 16;" :: "r"(d), "l"(g));
}
#define CP_COMMIT() asm volatile("cp.async.commit_group;")
#define CP_WAIT1()  asm volatile("cp.async.wait_group 1;")
#define CP_WAIT0()  asm volatile("cp.async.wait_group 0;")

// ============================================================================
// splitX: x[b,n,8] -> g_xf planes [i][b][n] (fp16)
// ============================================================================
__global__ __launch_bounds__(256)
void k_splitX(const float* __restrict__ x)
{
    size_t idx = blockIdx.x * 256 + threadIdx.x;    // (b,n)
    float x8[8];
    *(float4*)(x8)     = *(const float4*)(x + idx * 8);
    *(float4*)(x8 + 4) = *(const float4*)(x + idx * 8 + 4);
#pragma unroll
    for (int i = 0; i < 8; ++i)
        g_xf[(size_t)i * BN + idx] = __float2half(x8[i]);
}

// ============================================================================
// prepW (fused splitW + buildB), 2 n's per thread, half2 stores:
//   g_wrf[g][m][n] = fp16(w_right[m,n,g])
//   g_B[bj][m][t*512+n]: t<8 -> fp16(sign*weight[m,n,pp(t,bj)]), t=8 -> fp16(w_left[m,n,G[bj]])
// ============================================================================
__global__ __launch_bounds__(256)
void k_prepW(const float* __restrict__ weight, const float* __restrict__ w_left,
             const float* __restrict__ w_right)
{
    size_t idx2 = blockIdx.x * 256 + threadIdx.x;   // (m, n2): n2 = n/2
    int m = (int)(idx2 >> 8), n = (int)(idx2 & 255) * 2;
    size_t bn0 = (size_t)m * 512 + n;               // (m,n) flat
    float w[2][20], wl[2][4], wr[2][4];
#pragma unroll
    for (int j = 0; j < 2; ++j) {
#pragma unroll
        for (int q = 0; q < 5; ++q)
            *(float4*)(w[j] + q * 4) = *(const float4*)(weight + (bn0 + j) * 20 + q * 4);
        *(float4*)(wl[j]) = *(const float4*)(w_left + (bn0 + j) * 4);
        *(float4*)(wr[j]) = *(const float4*)(w_right + (bn0 + j) * 4);
    }

#pragma unroll
    for (int g = 0; g < 4; ++g)
        *(__half2*)(g_wrf + (size_t)g * N_IN * N_IN + bn0) =
            __floats2half2_rn(wr[0][g], wr[1][g]);

#pragma unroll
    for (int bj = 0; bj < 8; ++bj) {
        size_t base = ((size_t)bj * N_OUT + m) * KSL + n;
#pragma unroll
        for (int t = 0; t < 9; ++t) {
            float v0, v1;
            if (t < 8) {
                int bk = c_MS[c_MS[t] ^ c_MS[bj]];
                int e = t * 8 + bk;
                v0 = c_SG[e] ? w[0][c_P[e]] : -w[0][c_P[e]];
                v1 = c_SG[e] ? w[1][c_P[e]] : -w[1][c_P[e]];
            } else {
                v0 = wl[0][c_G[bj]];
                v1 = wl[1][c_G[bj]];
            }
            *(__half2*)(g_B + base + (size_t)t * 512) = __floats2half2_rn(v0, v1);
        }
    }
}

// ============================================================================
// Shared GEMM core: 128(b) x 128(m) CTA tile, 4 warps of 64x64, BK=64,
// 3-stage cp.async pipeline, single __syncthreads per k-iter, 128 threads.
// smem: 3 stages x (A 16KB + B 16KB) = 96KB dynamic.
// ============================================================================
struct GemmCtx {
    uint32_t smb;
    int lane, warp_m, warp_n;
    int ldrow, ldc16;
    uint32_t ld_sw;
    uint32_t a_lin, a_sw, a_kl;
    uint32_t b_lin, b_sw, b_kl;
    __device__ __forceinline__ void init(int tid) {
        lane = tid & 31;
        int wid = tid >> 5;
        warp_m = wid >> 1; warp_n = wid & 1;
        ldrow = tid >> 3; ldc16 = tid & 7;
        ld_sw = SWZ((uint32_t)(ldrow * 128 + ldc16 * 16));
        int a_r = warp_m * 64 + (lane & 7) + ((lane >> 3) & 1) * 8;
        a_lin = a_r * 128; a_sw = (a_r & 7) << 4; a_kl = (lane >> 4) * 16;
        int b_r = warp_n * 64 + (lane & 7) + (lane >> 4) * 8;
        b_lin = b_r * 128; b_sw = (b_r & 7) << 4; b_kl = ((lane >> 3) & 1) * 16;
    }
};

__device__ __forceinline__ void gemm_load(const GemmCtx& g, int s,
                                          const __half* Ap, size_t a_row0,
                                          const __half* Bp, size_t b_row0,
                                          size_t ldk, int kk) {
    const uint32_t sA = g.smb + (uint32_t)s * 32768u;
    const uint32_t sB = sA + 16384u;
#pragma unroll
    for (int j = 0; j < 8; ++j) {
        int row = g.ldrow + j * 16;
        cp16(sA + g.ld_sw + j * 2048u, Ap + a_row0 + (size_t)row * ldk + kk * 64 + g.ldc16 * 8);
        cp16(sB + g.ld_sw + j * 2048u, Bp + b_row0 + (size_t)row * ldk + kk * 64 + g.ldc16 * 8);
    }
    CP_COMMIT();
}

__device__ __forceinline__ void gemm_compute(const GemmCtx& g, int s, float c[4][8][4]) {
    const uint32_t sA = g.smb + (uint32_t)s * 32768u;
    const uint32_t sB = sA + 16384u;
#pragma unroll
    for (int k16 = 0; k16 < 4; ++k16) {
        uint32_t af[4][4], bf[4][4];
#pragma unroll
        for (int mi = 0; mi < 4; ++mi)
            ldm4(af[mi], sA + g.a_lin + mi * 2048u + ((k16 * 32u + g.a_kl) ^ g.a_sw));
#pragma unroll
        for (int nj = 0; nj < 4; ++nj)
            ldm4(bf[nj], sB + g.b_lin + nj * 2048u + ((k16 * 32u + g.b_kl) ^ g.b_sw));
#pragma unroll
        for (int mi = 0; mi < 4; ++mi)
#pragma unroll
            for (int nj = 0; nj < 4; ++nj) {
                mma_f16(c[mi][nj * 2 + 0], af[mi], bf[nj][0], bf[nj][1]);
                mma_f16(c[mi][nj * 2 + 1], af[mi], bf[nj][2], bf[nj][3]);
            }
    }
}

__device__ __forceinline__ void gemm_store(const GemmCtx& g, float c[4][8][4],
                                           float* base, int b0, int n0, int ldn) {
    const int mrow = b0 + g.warp_m * 64 + (g.lane >> 2);
    const int ncol = n0 + g.warp_n * 64 + (g.lane & 3) * 2;
#pragma unroll
    for (int mi = 0; mi < 4; ++mi)
#pragma unroll
        for (int n8 = 0; n8 < 8; ++n8) {
            float* p0 = base + (size_t)(mrow + mi * 16) * ldn + ncol + n8 * 8;
            float* p1 = base + (size_t)(mrow + mi * 16 + 8) * ldn + ncol + n8 * 8;
            *(float2*)p0 = make_float2(c[mi][n8][0], c[mi][n8][1]);
            *(float2*)p1 = make_float2(c[mi][n8][2], c[mi][n8][3]);
        }
}

// ============================================================================
// xr GEMM (tensor, single fp16): g_outT[i][b][m] = sum_n x[b,n,i]*w_right[m,n,G[i]]
// grid (4, 16, 8), 128 threads.
// ============================================================================
__global__ __launch_bounds__(128)
void k_gemm_xr()
{
    extern __shared__ char sm[];
    GemmCtx g; g.smb = smem_u32(sm); g.init(threadIdx.x);
    const int n0 = blockIdx.x * 128, b0 = blockIdx.y * 128;
    const int ib = blockIdx.z, gg = c_G[ib];

    const size_t a_row0 = ((size_t)ib * B_DIM + b0) * N_IN;
    const size_t b_row0 = ((size_t)gg * N_IN + n0) * N_IN;

    float c[4][8][4];
#pragma unroll
    for (int mi = 0; mi < 4; ++mi)
#pragma unroll
        for (int nn = 0; nn < 8; ++nn)
#pragma unroll
            for (int q = 0; q < 4; ++q) c[mi][nn][q] = 0.f;

    gemm_load(g, 0, g_xf, a_row0, g_wrf, b_row0, (size_t)N_IN, 0);
    gemm_load(g, 1, g_xf, a_row0, g_wrf, b_row0, (size_t)N_IN, 1);
#pragma unroll 1
    for (int kt = 0; kt < NKT_XR; ++kt) {
        if (kt + 1 < NKT_XR) CP_WAIT1(); else CP_WAIT0();
        __syncthreads();
        if (kt + 2 < NKT_XR)
            gemm_load(g, (kt + 2) % 3, g_xf, a_row0, g_wrf, b_row0, (size_t)N_IN, kt + 2);
        gemm_compute(g, kt % 3, c);
    }

    gemm_store(g, c, g_outT + (size_t)ib * B_DIM * N_IN, b0, n0, N_IN);
}

// ============================================================================
// buildA fused with normalization, 2 n's per thread, half2 stores:
//   read raw xr planes g_outT[i][b][n], normalize, combine with fp16 x planes,
//   emit A (fp16): A[bj][b][t*512+n] (t<8: x[t]*xr[bk], t=8: x[bj])
// ============================================================================
__global__ __launch_bounds__(256)
void k_buildA(const float* __restrict__ norm_a)
{
    size_t idx2 = blockIdx.x * 256 + threadIdx.x;   // (b, n2)
    int b = (int)(idx2 >> 8), n = (int)(idx2 & 255) * 2;
    size_t bn0 = (size_t)b * 512 + n;

    float r8[2][8];
#pragma unroll
    for (int i = 0; i < 8; ++i) {
        float2 v = *(const float2*)(g_outT + (size_t)i * BN + bn0);
        r8[0][i] = v.x; r8[1][i] = v.y;
    }

#pragma unroll
    for (int j = 0; j < 2; ++j) {
        float* r = r8[j];
        float n0 = fabsf(r[0]);
        float n1 = sqrtf(r[1]*r[1] + r[2]*r[2] + r[3]*r[3]);
        float n2 = sqrtf(r[4]*r[4] + r[5]*r[5] + r[6]*r[6]);
        float n3 = fabsf(r[7]);
        float4 na = *(const float4*)(norm_a + (n + j) * 4);
        float s0 = 1.f / (1.f + expf(-na.x));
        float s1 = 1.f / (1.f + expf(-na.y));
        float s2 = 1.f / (1.f + expf(-na.z));
        float s3 = 1.f / (1.f + expf(-na.w));
        float d0 = 1.f / (s0 * (n0 - 1.f) + 1.f + 1e-6f);
        float d1 = 1.f / (s1 * (n1 - 1.f) + 1.f + 1e-6f);
        float d2 = 1.f / (s2 * (n2 - 1.f) + 1.f + 1e-6f);
        float d3 = 1.f / (s3 * (n3 - 1.f) + 1.f + 1e-6f);
        r[0] *= d0; r[1] *= d1; r[2] *= d1; r[3] *= d1;
        r[4] *= d2; r[5] *= d2; r[6] *= d2; r[7] *= d3;
    }

    float x8[2][8];
#pragma unroll
    for (int i = 0; i < 8; ++i) {
        __half2 xv = *(const __half2*)(g_xf + (size_t)i * BN + bn0);
        float2 xf = __half22float2(xv);
        x8[0][i] = xf.x; x8[1][i] = xf.y;
    }

#pragma unroll
    for (int bj = 0; bj < 8; ++bj) {
        size_t base = ((size_t)bj * B_DIM + b) * KSL + n;
#pragma unroll
        for (int t = 0; t < 9; ++t) {
            float v0, v1;
            if (t < 8) {
                int bk = c_MS[c_MS[t] ^ c_MS[bj]];
                v0 = x8[0][t] * r8[0][bk];
                v1 = x8[1][t] * r8[1][bk];
            } else {
                v0 = x8[0][bj];
                v1 = x8[1][bj];
            }
            *(__half2*)(g_A + base + (size_t)t * 512) = __floats2half2_rn(v0, v1);
        }
    }
}

// ============================================================================
// main GEMM (tensor, single fp16 pass): g_outT[bj][b][m] = sum_k A[b,k]*B[m,k]
// grid (4, 16, 8), 128 threads, NKT=72.
// ============================================================================
__global__ __launch_bounds__(128)
void k_gemm()
{
    extern __shared__ char sm[];
    GemmCtx g; g.smb = smem_u32(sm); g.init(threadIdx.x);
    const int n0 = blockIdx.x * 128, b0 = blockIdx.y * 128;
    const int bj = blockIdx.z;

    const size_t a_row0 = ((size_t)bj * B_DIM + b0) * KSL;
    const size_t b_row0 = ((size_t)bj * N_OUT + n0) * KSL;

    float c[4][8][4];
#pragma unroll
    for (int mi = 0; mi < 4; ++mi)
#pragma unroll
        for (int nn = 0; nn < 8; ++nn)
#pragma unroll
            for (int q = 0; q < 4; ++q) c[mi][nn][q] = 0.f;

    gemm_load(g, 0, g_A, a_row0, g_B, b_row0, (size_t)KSL, 0);
    gemm_load(g, 1, g_A, a_row0, g_B, b_row0, (size_t)KSL, 1);
#pragma unroll 1
    for (int kt = 0; kt < NKT; ++kt) {
        if (kt + 1 < NKT) CP_WAIT1(); else CP_WAIT0();
        __syncthreads();
        if (kt + 2 < NKT)
            gemm_load(g, (kt + 2) % 3, g_A, a_row0, g_B, b_row0, (size_t)KSL, kt + 2);
        gemm_compute(g, kt % 3, c);
    }

    gemm_store(g, c, g_outT + (size_t)bj * B_DIM * N_OUT, b0, n0, N_OUT);
}

// ============================================================================
// merge: out[b][m][bj] = (g_outT[bj][b][m] + (bj==0)*b_left[m]) * RSQRT2
// ============================================================================
__global__ __launch_bounds__(256)
void k_merge(const float* __restrict__ b_left, float* __restrict__ out)
{
    size_t idx = blockIdx.x * 256 + threadIdx.x;
    int m = (int)(idx & 511);
    float v[8];
#pragma unroll
    for (int bj = 0; bj < 8; ++bj)
        v[bj] = g_outT[(size_t)bj * B_DIM * N_OUT + idx];
    v[0] += b_left[m];
    float* dst = out + idx * 8;
    *(float4*)(dst)     = make_float4(v[0]*RSQRT2, v[1]*RSQRT2, v[2]*RSQRT2, v[3]*RSQRT2);
    *(float4*)(dst + 4) = make_float4(v[4]*RSQRT2, v[5]*RSQRT2, v[6]*RSQRT2, v[7]*RSQRT2);
}

// ============================================================================
extern "C" void kernel_launch(void* const* d_in, const int* in_sizes, int n_in,
                              void* d_out, int out_size) {
    const float* x       = (const float*)d_in[0];
    const float* weight  = (const float*)d_in[1];
    const float* w_right = (const float*)d_in[2];
    const float* w_left  = (const float*)d_in[3];
    const float* b_left  = (const float*)d_in[4];
    const float* norm_a  = (const float*)d_in[5];
    float* out = (float*)d_out;

    cudaFuncSetAttribute(k_gemm,    cudaFuncAttributeMaxDynamicSharedMemorySize, 98304);
    cudaFuncSetAttribute(k_gemm_xr, cudaFuncAttributeMaxDynamicSharedMemorySize, 98304);

    k_splitX<<<(int)(BN / 256), 256>>>(x);
    k_prepW<<<(N_OUT * N_IN / 2) / 256, 256>>>(weight, w_left, w_right);
    dim3 gx(N_IN / 128, B_DIM / 128, 8);
    k_gemm_xr<<<gx, 128, 98304>>>();
    k_buildA<<<(int)(BN / 2 / 256), 256>>>(norm_a);
    dim3 gg(N_OUT / 128, B_DIM / 128, 8);
    k_gemm<<<gg, 128, 98304>>>();
    k_merge<<<(B_DIM * N_OUT) / 256, 256>>>(b_left, out);
}